// round 1
// baseline (speedup 1.0000x reference)
#include <cuda_runtime.h>
#include <math.h>

// ---------------- scratch (device globals; no allocations) ----------------
__device__ float g_P [8192*128];   // pos @ Wp1[:256]
__device__ float g_Q [8192*128];   // pos @ Wp1[256:]
__device__ float g_U0[8192*128];   // pos @ Wu1[:256]
__device__ float g_U1[4096*128];   // neg @ Wu1[256:]
__device__ float g_ue0[64*128];    // unary energies level-0
__device__ float g_tot[32*128*128];// pair totals scratch (max level 0)
__device__ float g_H  [32*64*128]; // gathered/averaged h for next level
__device__ float g_peA[32*64];
__device__ float g_ueA[32*64];
__device__ float g_peB[16*64];
__device__ float g_ueB[16*64];
__device__ int   g_subA[32*64*2];
__device__ int   g_subB[16*64*4];

// ---------------- SGEMM: C[M,128] = A[M,256] @ W[256,128] ----------------
// blockIdx.y selects which of the 4 GEMMs. BM=128,BN=128,BK=16, 256 thr, 8x8/thr.
__global__ __launch_bounds__(256) void gemm_all(
    const float* __restrict__ pos, const float* __restrict__ neg,
    const float* __restrict__ Wp1, const float* __restrict__ Wu1)
{
    const float* A; const float* W; float* C; int M;
    int g = blockIdx.y;
    if      (g == 0) { A = pos; W = Wp1;            C = g_P;  M = 8192; }
    else if (g == 1) { A = pos; W = Wp1 + 256*128;  C = g_Q;  M = 8192; }
    else if (g == 2) { A = pos; W = Wu1;            C = g_U0; M = 8192; }
    else             { A = neg; W = Wu1 + 256*128;  C = g_U1; M = 4096; }

    int row0 = blockIdx.x * 128;
    if (row0 >= M) return;

    __shared__ float sA[16][128];
    __shared__ float sB[16][128];

    int tid = threadIdx.x;
    int tx = tid & 15, ty = tid >> 4;
    float acc[8][8];
    #pragma unroll
    for (int i = 0; i < 8; i++)
        #pragma unroll
        for (int j = 0; j < 8; j++) acc[i][j] = 0.f;

    for (int k0 = 0; k0 < 256; k0 += 16) {
        #pragma unroll
        for (int i = 0; i < 2; i++) {           // A tile: 128 rows x 16 k
            int idx = tid * 2 + i;              // 0..511
            int r  = idx >> 2;
            int c4 = (idx & 3) * 4;
            float4 v = *(const float4*)(A + (size_t)(row0 + r) * 256 + k0 + c4);
            sA[c4+0][r] = v.x; sA[c4+1][r] = v.y; sA[c4+2][r] = v.z; sA[c4+3][r] = v.w;
        }
        #pragma unroll
        for (int i = 0; i < 2; i++) {           // W tile: 16 rows x 128 n
            int idx = tid * 2 + i;
            int r  = idx >> 5;
            int c4 = (idx & 31) * 4;
            *(float4*)&sB[r][c4] = *(const float4*)(W + (size_t)(k0 + r) * 128 + c4);
        }
        __syncthreads();
        #pragma unroll
        for (int k = 0; k < 16; k++) {
            float a[8], b[8];
            #pragma unroll
            for (int i = 0; i < 8; i++) a[i] = sA[k][ty*8 + i];
            #pragma unroll
            for (int j = 0; j < 8; j++) b[j] = sB[k][tx*8 + j];
            #pragma unroll
            for (int i = 0; i < 8; i++)
                #pragma unroll
                for (int j = 0; j < 8; j++) acc[i][j] = fmaf(a[i], b[j], acc[i][j]);
        }
        __syncthreads();
    }
    #pragma unroll
    for (int i = 0; i < 8; i++) {
        int r = row0 + ty*8 + i;
        float4 v0 = make_float4(acc[i][0], acc[i][1], acc[i][2], acc[i][3]);
        float4 v1 = make_float4(acc[i][4], acc[i][5], acc[i][6], acc[i][7]);
        *(float4*)(C + (size_t)r * 128 + tx*8    ) = v0;
        *(float4*)(C + (size_t)r * 128 + tx*8 + 4) = v1;
    }
}

// ---------------- unary energies: ue[b,m] = mean_n W2.relu(U0[b,m]+U1[b,n]+b1) + b2
__global__ __launch_bounds__(256) void ue_kernel(
    const float* __restrict__ bu1, const float* __restrict__ Wu2,
    const float* __restrict__ bu2)
{
    int b = blockIdx.x;
    int mbase = blockIdx.y * 32;
    __shared__ float sU1[64*128];
    __shared__ float red[8];
    int tid = threadIdx.x;
    int h = tid & 127;
    int half = tid >> 7;

    for (int i = tid; i < 64*128; i += 256)
        sU1[i] = g_U1[(size_t)b * 64 * 128 + i] + bu1[i & 127];
    float w2 = Wu2[h];
    float b2 = bu2[0];
    __syncthreads();

    for (int it = 0; it < 16; it++) {
        int m = mbase + it*2 + half;
        float u0 = g_U0[((size_t)b * 128 + m) * 128 + h];
        float a = 0.f;
        #pragma unroll 8
        for (int n = 0; n < 64; n++)
            a += fmaxf(u0 + sU1[n*128 + h], 0.f);
        float v = a * w2;
        #pragma unroll
        for (int off = 16; off; off >>= 1) v += __shfl_down_sync(0xffffffffu, v, off);
        int wid = tid >> 5;
        if ((tid & 31) == 0) red[wid] = v;
        __syncthreads();
        if ((tid & 127) == 0) {
            float t = red[half*4+0] + red[half*4+1] + red[half*4+2] + red[half*4+3];
            g_ue0[b * 128 + m] = t * (1.f/64.f) + b2;
        }
        __syncthreads();
    }
}

// ---------------- pair scores: tot[bn, m0*M+m1] = base0+base1 - W2.relu(H0+H1+b1) - b2
__global__ __launch_bounds__(256) void score_kernel(
    int lvl, int M, int Mc,
    const float* __restrict__ bp1, const float* __restrict__ Wp2,
    const float* __restrict__ bp2)
{
    const float *H0b, *H1b, *ue_in, *pe_in; int rs;
    if (lvl == 0) { H0b = g_P; H1b = g_Q; rs = 128*128; ue_in = g_ue0; pe_in = 0; }
    else if (lvl == 1) { H0b = g_H; H1b = g_H; rs = 64*128; ue_in = g_ueA; pe_in = g_peA; }
    else { H0b = g_H; H1b = g_H; rs = 64*128; ue_in = g_ueB; pe_in = g_peB; }

    extern __shared__ float sm[];
    int bn = blockIdx.y;
    int m0off = blockIdx.x * Mc;
    float* sH0 = sm;                  // Mc*129
    float* sH1 = sH0 + Mc*129;        // M*129
    float* sw2 = sH1 + M*129;         // 128
    float* sb0 = sw2 + 128;           // Mc
    float* sb1 = sb0 + Mc;            // M

    const float* h0 = H0b + (size_t)(2*bn  ) * rs + (size_t)m0off * 128;
    const float* h1 = H1b + (size_t)(2*bn+1) * rs;
    int tid = threadIdx.x;

    for (int i = tid; i < Mc*128; i += 256) {
        int m = i >> 7, hh = i & 127;
        sH0[m*129 + hh] = h0[i];
    }
    for (int i = tid; i < M*128; i += 256) {
        int m = i >> 7, hh = i & 127;
        sH1[m*129 + hh] = h1[i] + bp1[hh];
    }
    if (tid < 128) sw2[tid] = Wp2[tid];
    float b2 = bp2[0];
    for (int i = tid; i < Mc; i += 256) {
        int gm = (2*bn) * M + m0off + i;
        sb0[i] = ue_in[gm] + (pe_in ? pe_in[gm] : 0.f) - b2;
    }
    for (int i = tid; i < M; i += 256) {
        int gm = (2*bn+1) * M + i;
        sb1[i] = ue_in[gm] + (pe_in ? pe_in[gm] : 0.f);
    }
    __syncthreads();

    int t1 = M >> 2;
    int ntiles = (Mc >> 2) * t1;
    float* out = g_tot + (size_t)bn * M * M;
    for (int t = tid; t < ntiles; t += 256) {
        int tm0 = (t / t1) * 4;
        int tm1 = (t % t1) * 4;
        const float* p0 = sH0 + tm0*129;
        const float* p1 = sH1 + tm1*129;
        float acc[4][4];
        #pragma unroll
        for (int i = 0; i < 4; i++)
            #pragma unroll
            for (int j = 0; j < 4; j++) acc[i][j] = 0.f;
        for (int hh = 0; hh < 128; hh++) {
            float w = sw2[hh];
            float a[4], bb[4];
            #pragma unroll
            for (int i = 0; i < 4; i++) a[i]  = p0[i*129 + hh];
            #pragma unroll
            for (int j = 0; j < 4; j++) bb[j] = p1[j*129 + hh];
            #pragma unroll
            for (int i = 0; i < 4; i++)
                #pragma unroll
                for (int j = 0; j < 4; j++)
                    acc[i][j] = fmaf(w, fmaxf(a[i] + bb[j], 0.f), acc[i][j]);
        }
        #pragma unroll
        for (int i = 0; i < 4; i++)
            #pragma unroll
            for (int j = 0; j < 4; j++)
                out[(size_t)(m0off + tm0 + i) * M + tm1 + j]
                    = sb0[tm0 + i] + sb1[tm1 + j] - acc[i][j];
    }
}

// ---------------- top-k (exact jax order: ascending value, ties by index) +
//                   carry pe/ue/sub + gather next-level Havg (fused)
__global__ __launch_bounds__(256) void topk_kernel(
    int lvl, int M, int K, int S_in, int last, float* __restrict__ d_out)
{
    const int* sub_in; const float* ue_in;
    float *pe_out, *ue_out, *Hout; int* sub_out;
    if (lvl == 0) { sub_in = 0;      ue_in = g_ue0; pe_out = g_peA; ue_out = g_ueA; sub_out = g_subA; Hout = g_H; }
    else if (lvl == 1) { sub_in = g_subA; ue_in = g_ueA; pe_out = g_peB; ue_out = g_ueB; sub_out = g_subB; Hout = g_H; }
    else { sub_in = g_subB; ue_in = g_ueB; pe_out = g_peA; ue_out = g_ueA; sub_out = g_subA; Hout = 0; }

    extern __shared__ float sm[];
    int bn = blockIdx.x;
    int MM = M * M;
    float* stot  = sm;                       // MM
    float* lminv = stot + MM;                // 256
    int*   lmini = (int*)(lminv + 256);      // 256
    float* selv  = (float*)(lmini + 256);    // 64
    int*   selj  = (int*)(selv + 64);        // 64
    int*   subnew= selj + 64;                // up to 512 ints
    __shared__ float s_winv; __shared__ int s_wini;

    int tid = threadIdx.x;
    const float* tsrc = g_tot + (size_t)bn * MM;
    for (int i = tid; i < MM; i += 256) stot[i] = tsrc[i];
    __syncthreads();

    int chunk = MM / 256;
    int c0 = tid * chunk;
    {
        float bv = stot[c0]; int bi = c0;
        for (int i = 1; i < chunk; i++) {
            float v = stot[c0 + i];
            if (v < bv) { bv = v; bi = c0 + i; }
        }
        lminv[tid] = bv; lmini[tid] = bi;
    }
    __syncthreads();

    const float INF = INFINITY;
    for (int r = 0; r < K; r++) {
        if (tid < 32) {
            float bv = lminv[tid]; int bi = lmini[tid];
            for (int i = tid + 32; i < 256; i += 32) {
                float v = lminv[i]; int vi = lmini[i];
                if (v < bv || (v == bv && vi < bi)) { bv = v; bi = vi; }
            }
            #pragma unroll
            for (int off = 16; off; off >>= 1) {
                float ov = __shfl_down_sync(0xffffffffu, bv, off);
                int   oi = __shfl_down_sync(0xffffffffu, bi, off);
                if (ov < bv || (ov == bv && oi < bi)) { bv = ov; bi = oi; }
            }
            if (tid == 0) { s_winv = bv; s_wini = bi; selj[r] = bi; selv[r] = bv; }
        }
        __syncthreads();
        int j = s_wini;
        int owner = j / chunk;
        if (tid == owner) {
            stot[j] = INF;
            float bv = INF; int bi = c0;
            for (int i = 0; i < chunk; i++) {
                float v = stot[c0 + i];
                if (v < bv) { bv = v; bi = c0 + i; }
            }
            lminv[tid] = bv; lmini[tid] = bi;
        }
        __syncthreads();
    }

    int S2 = 2 * S_in;
    if (tid < K) {
        int j = selj[tid]; int m0 = j / M, m1 = j % M;
        float u0 = ue_in[(2*bn) * M + m0];
        float u1 = ue_in[(2*bn+1) * M + m1];
        float uen = u0 + u1;
        ue_out[bn * K + tid] = uen;
        pe_out[bn * K + tid] = selv[tid] - uen;
        if (sub_in) {
            for (int s = 0; s < S_in; s++) {
                subnew[tid*S2 + s]        = sub_in[((2*bn) * M + m0) * S_in + s];
                subnew[tid*S2 + S_in + s] = sub_in[((2*bn+1) * M + m1) * S_in + s];
            }
        } else {
            subnew[tid*2] = m0; subnew[tid*2 + 1] = m1;
        }
        for (int s = 0; s < S2; s++)
            sub_out[(bn * K + tid) * S2 + s] = subnew[tid*S2 + s];
    }
    __syncthreads();

    if (Hout) {  // gather+average for the next level
        const float* X = (bn & 1) ? g_Q : g_P;
        float inv = 1.f / (float)S2;
        for (int idx = tid; idx < K * 128; idx += 256) {
            int r = idx >> 7, h = idx & 127;
            float s = 0.f;
            for (int s2 = 0; s2 < S2; s2++)
                s += X[((size_t)(bn * S2 + s2) * 128 + subnew[r*S2 + s2]) * 128 + h];
            Hout[((size_t)bn * K + r) * 128 + h] = s * inv;
        }
    }
    if (last && tid < S2)
        d_out[bn * S2 + tid] = (float)subnew[tid];
}

// ---------------- is_target ----------------
__global__ __launch_bounds__(256) void istarget_kernel(
    const int* __restrict__ pos_classes, const int* __restrict__ target,
    float* __restrict__ out)
{
    int i = blockIdx.x * 256 + threadIdx.x;
    if (i < 8192) {
        int b = i >> 10;
        out[64 + i] = (pos_classes[i] == target[b]) ? 1.f : 0.f;
    }
}

// ---------------- launch ----------------
extern "C" void kernel_launch(void* const* d_in, const int* in_sizes, int n_in,
                              void* d_out, int out_size)
{
    const float* pos  = (const float*)d_in[0];
    const float* neg  = (const float*)d_in[1];
    const int*   pcls = (const int*)  d_in[2];
    const int*   tcls = (const int*)  d_in[3];
    const float* Wp1  = (const float*)d_in[4];
    const float* bp1  = (const float*)d_in[5];
    const float* Wp2  = (const float*)d_in[6];
    const float* bp2  = (const float*)d_in[7];
    const float* Wu1  = (const float*)d_in[8];
    const float* bu1  = (const float*)d_in[9];
    const float* Wu2  = (const float*)d_in[10];
    const float* bu2  = (const float*)d_in[11];
    float* out = (float*)d_out;

    cudaFuncSetAttribute(score_kernel, cudaFuncAttributeMaxDynamicSharedMemorySize, 84000);
    cudaFuncSetAttribute(topk_kernel,  cudaFuncAttributeMaxDynamicSharedMemorySize, 71000);

    // 1) four SGEMMs: P, Q, U0, U1
    gemm_all<<<dim3(64, 4), 256>>>(pos, neg, Wp1, Wu1);
    // 2) unary energies
    ue_kernel<<<dim3(64, 4), 256>>>(bu1, Wu2, bu2);

    // smem sizes (floats): score lvl0: 32*129+128*129+128+32+128 ; lvl1/2: 64*129*2+256
    size_t smS0 = (size_t)(32*129 + 128*129 + 128 + 32 + 128) * 4;
    size_t smS1 = (size_t)(64*129 + 64*129 + 128 + 64 + 64) * 4;
    size_t smT0 = (size_t)(128*128 + 256 + 256 + 64 + 64 + 512) * 4;
    size_t smT1 = (size_t)(64*64   + 256 + 256 + 64 + 64 + 512) * 4;

    // level 0: M=128, Bn=32, K=64
    score_kernel<<<dim3(4, 32), 256, smS0>>>(0, 128, 32, bp1, Wp2, bp2);
    topk_kernel <<<32, 256, smT0>>>(0, 128, 64, 1, 0, out);
    // level 1: M=64, Bn=16, K=64
    score_kernel<<<dim3(1, 16), 256, smS1>>>(1, 64, 64, bp1, Wp2, bp2);
    topk_kernel <<<16, 256, smT1>>>(1, 64, 64, 2, 0, out);
    // level 2: M=64, Bn=8, K=1 (final; writes sub[:,0] as floats to out[0..63])
    score_kernel<<<dim3(1, 8), 256, smS1>>>(2, 64, 64, bp1, Wp2, bp2);
    topk_kernel <<<8, 256, smT1>>>(2, 64, 1, 4, 1, out);

    // is_target -> out[64 .. 64+8192)
    istarget_kernel<<<32, 256>>>(pcls, tcls, out);
}

// round 2
// speedup vs baseline: 1.2363x; 1.2363x over previous
#include <cuda_runtime.h>
#include <math.h>

// ---------------- scratch (device globals; no allocations) ----------------
__device__ float g_P [8192*128];   // pos @ Wp1[:256]
__device__ float g_Q [8192*128];   // pos @ Wp1[256:]
__device__ float g_U0[8192*128];   // pos @ Wu1[:256]
__device__ float g_U1[4096*128];   // neg @ Wu1[256:]
__device__ float g_ue0[64*128];    // unary energies level-0
__device__ float g_tot[32*128*128];// pair totals scratch (max level 0)
__device__ float g_H  [32*64*128]; // gathered/averaged h for next level
__device__ float g_peA[32*64];
__device__ float g_ueA[32*64];
__device__ float g_peB[16*64];
__device__ float g_ueB[16*64];
__device__ int   g_subA[32*64*2];
__device__ int   g_subB[16*64*4];

// ---------------- f32x2 packed helpers ----------------
__device__ __forceinline__ unsigned long long pk2(float x, float y) {
    unsigned long long r;
    asm("mov.b64 %0, {%1,%2};" : "=l"(r) : "f"(x), "f"(y));
    return r;
}
__device__ __forceinline__ void fma2(unsigned long long &d,
                                     unsigned long long a, unsigned long long b) {
    asm("fma.rn.f32x2 %0, %1, %2, %0;" : "+l"(d) : "l"(a), "l"(b));
}
__device__ __forceinline__ void upk2(unsigned long long v, float &lo, float &hi) {
    asm("mov.b64 {%0,%1}, %2;" : "=f"(lo), "=f"(hi) : "l"(v));
}

// ---------------- SGEMM: C[M,128] = A[M,256] @ W[256,128] ----------------
// blockIdx.y selects which of the 4 GEMMs. BM=128,BN=128,BK=16, 256 thr, 8x8/thr.
// Inner product done with fma.rn.f32x2 (FFMA2): 32 packed FMAs instead of 64.
__global__ __launch_bounds__(256) void gemm_all(
    const float* __restrict__ pos, const float* __restrict__ neg,
    const float* __restrict__ Wp1, const float* __restrict__ Wu1)
{
    const float* A; const float* W; float* C; int M;
    int g = blockIdx.y;
    if      (g == 0) { A = pos; W = Wp1;            C = g_P;  M = 8192; }
    else if (g == 1) { A = pos; W = Wp1 + 256*128;  C = g_Q;  M = 8192; }
    else if (g == 2) { A = pos; W = Wu1;            C = g_U0; M = 8192; }
    else             { A = neg; W = Wu1 + 256*128;  C = g_U1; M = 4096; }

    int row0 = blockIdx.x * 128;
    if (row0 >= M) return;

    __shared__ float sA[16][128];
    __shared__ float sB[16][128];

    int tid = threadIdx.x;
    int tx = tid & 15, ty = tid >> 4;

    unsigned long long acc2[8][4];
    #pragma unroll
    for (int i = 0; i < 8; i++)
        #pragma unroll
        for (int j = 0; j < 4; j++) acc2[i][j] = 0ull;

    for (int k0 = 0; k0 < 256; k0 += 16) {
        #pragma unroll
        for (int i = 0; i < 2; i++) {           // A tile: 128 rows x 16 k
            int idx = tid * 2 + i;              // 0..511
            int r  = idx >> 2;
            int c4 = (idx & 3) * 4;
            float4 v = *(const float4*)(A + (size_t)(row0 + r) * 256 + k0 + c4);
            sA[c4+0][r] = v.x; sA[c4+1][r] = v.y; sA[c4+2][r] = v.z; sA[c4+3][r] = v.w;
        }
        #pragma unroll
        for (int i = 0; i < 2; i++) {           // W tile: 16 rows x 128 n
            int idx = tid * 2 + i;
            int r  = idx >> 5;
            int c4 = (idx & 31) * 4;
            *(float4*)&sB[r][c4] = *(const float4*)(W + (size_t)(k0 + r) * 128 + c4);
        }
        __syncthreads();
        #pragma unroll
        for (int k = 0; k < 16; k++) {
            float4 a0 = *(const float4*)&sA[k][ty*8];
            float4 a1 = *(const float4*)&sA[k][ty*8 + 4];
            float4 b0 = *(const float4*)&sB[k][tx*8];
            float4 b1 = *(const float4*)&sB[k][tx*8 + 4];
            unsigned long long bp[4];
            bp[0] = pk2(b0.x, b0.y); bp[1] = pk2(b0.z, b0.w);
            bp[2] = pk2(b1.x, b1.y); bp[3] = pk2(b1.z, b1.w);
            float av[8] = {a0.x, a0.y, a0.z, a0.w, a1.x, a1.y, a1.z, a1.w};
            #pragma unroll
            for (int i = 0; i < 8; i++) {
                unsigned long long ap = pk2(av[i], av[i]);
                #pragma unroll
                for (int j = 0; j < 4; j++) fma2(acc2[i][j], ap, bp[j]);
            }
        }
        __syncthreads();
    }
    #pragma unroll
    for (int i = 0; i < 8; i++) {
        int r = row0 + ty*8 + i;
        float c[8];
        #pragma unroll
        for (int j = 0; j < 4; j++) upk2(acc2[i][j], c[2*j], c[2*j+1]);
        float4 v0 = make_float4(c[0], c[1], c[2], c[3]);
        float4 v1 = make_float4(c[4], c[5], c[6], c[7]);
        *(float4*)(C + (size_t)r * 128 + tx*8    ) = v0;
        *(float4*)(C + (size_t)r * 128 + tx*8 + 4) = v1;
    }
}

// ---------------- unary energies: ue[b,m] = mean_n W2.relu(U0[b,m]+U1[b,n]+b1) + b2
__global__ __launch_bounds__(256) void ue_kernel(
    const float* __restrict__ bu1, const float* __restrict__ Wu2,
    const float* __restrict__ bu2)
{
    int b = blockIdx.x;
    int mbase = blockIdx.y * 32;
    __shared__ float sU1[64*128];
    __shared__ float red[8];
    int tid = threadIdx.x;
    int h = tid & 127;
    int half = tid >> 7;

    for (int i = tid; i < 64*128; i += 256)
        sU1[i] = g_U1[(size_t)b * 64 * 128 + i] + bu1[i & 127];
    float w2 = Wu2[h];
    float b2 = bu2[0];
    __syncthreads();

    for (int it = 0; it < 16; it++) {
        int m = mbase + it*2 + half;
        float u0 = g_U0[((size_t)b * 128 + m) * 128 + h];
        float a = 0.f;
        #pragma unroll 8
        for (int n = 0; n < 64; n++)
            a += fmaxf(u0 + sU1[n*128 + h], 0.f);
        float v = a * w2;
        #pragma unroll
        for (int off = 16; off; off >>= 1) v += __shfl_down_sync(0xffffffffu, v, off);
        int wid = tid >> 5;
        if ((tid & 31) == 0) red[wid] = v;
        __syncthreads();
        if ((tid & 127) == 0) {
            float t = red[half*4+0] + red[half*4+1] + red[half*4+2] + red[half*4+3];
            g_ue0[b * 128 + m] = t * (1.f/64.f) + b2;
        }
        __syncthreads();
    }
}

// ---------------- pair scores: tot[bn, m0*M+m1] = base0+base1 - W2.relu(H0+H1+b1) - b2
__global__ __launch_bounds__(256) void score_kernel(
    int lvl, int M, int Mc,
    const float* __restrict__ bp1, const float* __restrict__ Wp2,
    const float* __restrict__ bp2)
{
    const float *H0b, *H1b, *ue_in, *pe_in; int rs;
    if (lvl == 0) { H0b = g_P; H1b = g_Q; rs = 128*128; ue_in = g_ue0; pe_in = 0; }
    else if (lvl == 1) { H0b = g_H; H1b = g_H; rs = 64*128; ue_in = g_ueA; pe_in = g_peA; }
    else { H0b = g_H; H1b = g_H; rs = 64*128; ue_in = g_ueB; pe_in = g_peB; }

    extern __shared__ float sm[];
    int bn = blockIdx.y;
    int m0off = blockIdx.x * Mc;
    float* sH0 = sm;                  // Mc*129
    float* sH1 = sH0 + Mc*129;        // M*129
    float* sw2 = sH1 + M*129;         // 128
    float* sb0 = sw2 + 128;           // Mc
    float* sb1 = sb0 + Mc;            // M

    const float* h0 = H0b + (size_t)(2*bn  ) * rs + (size_t)m0off * 128;
    const float* h1 = H1b + (size_t)(2*bn+1) * rs;
    int tid = threadIdx.x;

    for (int i = tid; i < Mc*128; i += 256) {
        int m = i >> 7, hh = i & 127;
        sH0[m*129 + hh] = h0[i];
    }
    for (int i = tid; i < M*128; i += 256) {
        int m = i >> 7, hh = i & 127;
        sH1[m*129 + hh] = h1[i] + bp1[hh];
    }
    if (tid < 128) sw2[tid] = Wp2[tid];
    float b2 = bp2[0];
    for (int i = tid; i < Mc; i += 256) {
        int gm = (2*bn) * M + m0off + i;
        sb0[i] = ue_in[gm] + (pe_in ? pe_in[gm] : 0.f) - b2;
    }
    for (int i = tid; i < M; i += 256) {
        int gm = (2*bn+1) * M + i;
        sb1[i] = ue_in[gm] + (pe_in ? pe_in[gm] : 0.f);
    }
    __syncthreads();

    int t1 = M >> 2;
    int ntiles = (Mc >> 2) * t1;
    float* out = g_tot + (size_t)bn * M * M;
    for (int t = tid; t < ntiles; t += 256) {
        int tm0 = (t / t1) * 4;
        int tm1 = (t % t1) * 4;
        const float* p0 = sH0 + tm0*129;
        const float* p1 = sH1 + tm1*129;
        float acc[4][4];
        #pragma unroll
        for (int i = 0; i < 4; i++)
            #pragma unroll
            for (int j = 0; j < 4; j++) acc[i][j] = 0.f;
        for (int hh = 0; hh < 128; hh++) {
            float w = sw2[hh];
            float a[4], bb[4];
            #pragma unroll
            for (int i = 0; i < 4; i++) a[i]  = p0[i*129 + hh];
            #pragma unroll
            for (int j = 0; j < 4; j++) bb[j] = p1[j*129 + hh];
            #pragma unroll
            for (int i = 0; i < 4; i++)
                #pragma unroll
                for (int j = 0; j < 4; j++)
                    acc[i][j] = fmaf(w, fmaxf(a[i] + bb[j], 0.f), acc[i][j]);
        }
        #pragma unroll
        for (int i = 0; i < 4; i++)
            #pragma unroll
            for (int j = 0; j < 4; j++)
                out[(size_t)(m0off + tm0 + i) * M + tm1 + j]
                    = sb0[tm0 + i] + sb1[tm1 + j] - acc[i][j];
    }
}

// ---------------- top-k via exact radix select ----------------
// Exactly reproduces jax.lax.top_k(-total): ascending total, ties by ascending index.
// Monotone key transform: neg -> ~bits, non-neg -> bits|0x80000000 (unsigned order == float order).
__global__ __launch_bounds__(256) void topk_kernel(
    int lvl, int M, int K, int S_in, int last, float* __restrict__ d_out)
{
    const int* sub_in; const float* ue_in;
    float *pe_out, *ue_out, *Hout; int* sub_out;
    if (lvl == 0) { sub_in = 0;      ue_in = g_ue0; pe_out = g_peA; ue_out = g_ueA; sub_out = g_subA; Hout = g_H; }
    else if (lvl == 1) { sub_in = g_subA; ue_in = g_ueA; pe_out = g_peB; ue_out = g_ueB; sub_out = g_subB; Hout = g_H; }
    else { sub_in = g_subB; ue_in = g_ueB; pe_out = g_peA; ue_out = g_ueA; sub_out = g_subA; Hout = 0; }

    extern __shared__ unsigned smu[];
    int bn = blockIdx.x;
    int MM = M * M;
    unsigned* skeys  = smu;                      // MM
    int*      bins   = (int*)(skeys + MM);       // 256
    unsigned* selk   = (unsigned*)(bins + 256);  // 64
    int*      seli   = (int*)(selk + 64);        // 64
    int*      tiebuf = seli + 64;                // 512
    int*      subnew = tiebuf + 512;             // 512
    int*      sortedj= subnew + 512;             // 64
    float*    sortedv= (float*)(sortedj + 64);   // 64
    int*      redi   = (int*)(sortedv + 64);     // 256

    __shared__ unsigned s_prefix;
    __shared__ int s_rem, s_cnt, s_tcnt;

    int tid = threadIdx.x;
    const float* tsrc = g_tot + (size_t)bn * MM;
    for (int i = tid; i < MM; i += 256) {
        unsigned b = __float_as_uint(tsrc[i]);
        skeys[i] = (b & 0x80000000u) ? ~b : (b | 0x80000000u);
    }
    if (tid == 0) { s_prefix = 0u; s_rem = K; s_cnt = 0; s_tcnt = 0; }
    __syncthreads();

    // 4 MSB-first radix passes of 8 bits: find K-th smallest key + tie rank
    #pragma unroll
    for (int pass = 0; pass < 4; pass++) {
        int shift = 24 - 8 * pass;
        bins[tid] = 0;
        if (tid < 0) {}  // (256 bins == 256 threads)
        __syncthreads();
        unsigned pmask = (pass == 0) ? 0u : (0xFFFFFFFFu << (shift + 8));
        unsigned pref = s_prefix;
        for (int i = tid; i < MM; i += 256) {
            unsigned k = skeys[i];
            if ((k & pmask) == pref)
                atomicAdd(&bins[(k >> shift) & 255], 1);
        }
        __syncthreads();
        if (tid == 0) {
            int cum = 0, b = 0;
            for (; b < 256; b++) {
                int c = bins[b];
                if (cum + c >= s_rem) break;
                cum += c;
            }
            s_rem -= cum;
            s_prefix = pref | ((unsigned)b << shift);
        }
        __syncthreads();
    }
    unsigned T = s_prefix;
    int rem = s_rem;                // # of key==T elements to include (smallest indices)

    // collect winners: key < T unconditionally; key == T into tie buffer
    for (int i = tid; i < MM; i += 256) {
        unsigned k = skeys[i];
        if (k < T) {
            int p = atomicAdd(&s_cnt, 1);
            selk[p] = k; seli[p] = i;
        } else if (k == T) {
            int p = atomicAdd(&s_tcnt, 1);
            if (p < 512) tiebuf[p] = i;
        }
    }
    __syncthreads();
    int c = s_cnt;                  // == K - rem
    int tn = min(s_tcnt, 512);
    for (int r = 0; r < rem; r++) { // usually 1 iteration
        int bi = 0x7fffffff;
        for (int j = tid; j < tn; j += 256) bi = min(bi, tiebuf[j]);
        redi[tid] = bi;
        __syncthreads();
        #pragma unroll
        for (int s = 128; s; s >>= 1) {
            if (tid < s) redi[tid] = min(redi[tid], redi[tid + s]);
            __syncthreads();
        }
        int w = redi[0];
        if (tid == 0) { selk[c + r] = T; seli[c + r] = w; }
        for (int j = tid; j < tn; j += 256)
            if (tiebuf[j] == w) tiebuf[j] = 0x7fffffff;
        __syncthreads();
    }

    // rank-sort the K winners by (key asc, index asc)
    if (tid < K) {
        unsigned k = selk[tid]; int idx = seli[tid];
        int rank = 0;
        for (int j = 0; j < K; j++) {
            unsigned kj = selk[j]; int ij = seli[j];
            if (kj < k || (kj == k && ij < idx)) rank++;
        }
        sortedj[rank] = idx;
        unsigned b = (k & 0x80000000u) ? (k & 0x7FFFFFFFu) : ~k;
        sortedv[rank] = __uint_as_float(b);
    }
    __syncthreads();

    int S2 = 2 * S_in;
    if (tid < K) {
        int j = sortedj[tid]; int m0 = j / M, m1 = j % M;
        float u0 = ue_in[(2*bn) * M + m0];
        float u1 = ue_in[(2*bn+1) * M + m1];
        float uen = u0 + u1;
        ue_out[bn * K + tid] = uen;
        pe_out[bn * K + tid] = sortedv[tid] - uen;
        if (sub_in) {
            for (int s = 0; s < S_in; s++) {
                subnew[tid*S2 + s]        = sub_in[((2*bn) * M + m0) * S_in + s];
                subnew[tid*S2 + S_in + s] = sub_in[((2*bn+1) * M + m1) * S_in + s];
            }
        } else {
            subnew[tid*2] = m0; subnew[tid*2 + 1] = m1;
        }
        for (int s = 0; s < S2; s++)
            sub_out[(bn * K + tid) * S2 + s] = subnew[tid*S2 + s];
    }
    __syncthreads();

    if (Hout) {  // gather+average for the next level
        const float* X = (bn & 1) ? g_Q : g_P;
        float inv = 1.f / (float)S2;
        for (int idx = tid; idx < K * 128; idx += 256) {
            int r = idx >> 7, h = idx & 127;
            float s = 0.f;
            for (int s2 = 0; s2 < S2; s2++)
                s += X[((size_t)(bn * S2 + s2) * 128 + subnew[r*S2 + s2]) * 128 + h];
            Hout[((size_t)bn * K + r) * 128 + h] = s * inv;
        }
    }
    if (last && tid < S2)
        d_out[bn * S2 + tid] = (float)subnew[tid];
}

// ---------------- is_target ----------------
__global__ __launch_bounds__(256) void istarget_kernel(
    const int* __restrict__ pos_classes, const int* __restrict__ target,
    float* __restrict__ out)
{
    int i = blockIdx.x * 256 + threadIdx.x;
    if (i < 8192) {
        int b = i >> 10;
        out[64 + i] = (pos_classes[i] == target[b]) ? 1.f : 0.f;
    }
}

// ---------------- launch ----------------
extern "C" void kernel_launch(void* const* d_in, const int* in_sizes, int n_in,
                              void* d_out, int out_size)
{
    const float* pos  = (const float*)d_in[0];
    const float* neg  = (const float*)d_in[1];
    const int*   pcls = (const int*)  d_in[2];
    const int*   tcls = (const int*)  d_in[3];
    const float* Wp1  = (const float*)d_in[4];
    const float* bp1  = (const float*)d_in[5];
    const float* Wp2  = (const float*)d_in[6];
    const float* bp2  = (const float*)d_in[7];
    const float* Wu1  = (const float*)d_in[8];
    const float* bu1  = (const float*)d_in[9];
    const float* Wu2  = (const float*)d_in[10];
    const float* bu2  = (const float*)d_in[11];
    float* out = (float*)d_out;

    cudaFuncSetAttribute(score_kernel, cudaFuncAttributeMaxDynamicSharedMemorySize, 84000);
    cudaFuncSetAttribute(topk_kernel,  cudaFuncAttributeMaxDynamicSharedMemorySize, 96000);

    // 1) four SGEMMs: P, Q, U0, U1
    gemm_all<<<dim3(64, 4), 256>>>(pos, neg, Wp1, Wu1);
    // 2) unary energies
    ue_kernel<<<dim3(64, 4), 256>>>(bu1, Wu2, bu2);

    size_t smS0 = (size_t)(32*129 + 128*129 + 128 + 32 + 128) * 4;
    size_t smS1 = (size_t)(64*129 + 64*129 + 128 + 64 + 64) * 4;
    size_t smT0 = (size_t)(128*128 + 1792) * 4;   // 72704
    size_t smT1 = (size_t)(64*64   + 1792) * 4;   // 23552

    // level 0: M=128, Bn=32, K=64
    score_kernel<<<dim3(4, 32), 256, smS0>>>(0, 128, 32, bp1, Wp2, bp2);
    topk_kernel <<<32, 256, smT0>>>(0, 128, 64, 1, 0, out);
    // level 1: M=64, Bn=16, K=64
    score_kernel<<<dim3(1, 16), 256, smS1>>>(1, 64, 64, bp1, Wp2, bp2);
    topk_kernel <<<16, 256, smT1>>>(1, 64, 64, 2, 0, out);
    // level 2: M=64, Bn=8, K=1 (final; writes sub[:,0] as floats to out[0..63])
    score_kernel<<<dim3(1, 8), 256, smS1>>>(2, 64, 64, bp1, Wp2, bp2);
    topk_kernel <<<8, 256, smT1>>>(2, 64, 1, 4, 1, out);

    // is_target -> out[64 .. 64+8192)
    istarget_kernel<<<32, 256>>>(pcls, tcls, out);
}

// round 3
// speedup vs baseline: 1.4680x; 1.1874x over previous
#include <cuda_runtime.h>
#include <math.h>

typedef unsigned long long ull;
#define ABS2 0x7FFFFFFF7FFFFFFFULL

// ---------------- scratch (device globals; no allocations) ----------------
__device__ float g_P [8192*128];   // pos @ Wp1[:256]
__device__ float g_Q [8192*128];   // pos @ Wp1[256:]
__device__ float g_U0[8192*128];   // pos @ Wu1[:256]
__device__ float g_U1[4096*128];   // neg @ Wu1[256:]
__device__ float g_ue0[64*128];    // unary energies level-0
__device__ float g_tot[32*128*128];// pair totals (level 0 only)
__device__ float g_H  [32*64*128]; // gathered/averaged h for next level
__device__ float g_peA[32*64];
__device__ float g_ueA[32*64];
__device__ float g_peB[16*64];
__device__ float g_ueB[16*64];
__device__ int   g_subA[32*64*2];
__device__ int   g_subB[16*64*4];

// ---------------- f32x2 packed helpers ----------------
__device__ __forceinline__ ull pk2(float x, float y) {
    ull r; asm("mov.b64 %0, {%1,%2};" : "=l"(r) : "f"(x), "f"(y)); return r;
}
__device__ __forceinline__ void upk2(ull v, float &lo, float &hi) {
    asm("mov.b64 {%0,%1}, %2;" : "=f"(lo), "=f"(hi) : "l"(v));
}
__device__ __forceinline__ ull add2(ull a, ull b) {
    ull r; asm("add.rn.f32x2 %0, %1, %2;" : "=l"(r) : "l"(a), "l"(b)); return r;
}
__device__ __forceinline__ void fma2(ull &d, ull a, ull b) {
    asm("fma.rn.f32x2 %0, %1, %2, %0;" : "+l"(d) : "l"(a), "l"(b));
}

// ---------------- SGEMM: C[M,128] = A[M,256] @ W[256,128] (f32x2) ----------
__global__ __launch_bounds__(256) void gemm_all(
    const float* __restrict__ pos, const float* __restrict__ neg,
    const float* __restrict__ Wp1, const float* __restrict__ Wu1)
{
    const float* A; const float* W; float* C; int M;
    int g = blockIdx.y;
    if      (g == 0) { A = pos; W = Wp1;            C = g_P;  M = 8192; }
    else if (g == 1) { A = pos; W = Wp1 + 256*128;  C = g_Q;  M = 8192; }
    else if (g == 2) { A = pos; W = Wu1;            C = g_U0; M = 8192; }
    else             { A = neg; W = Wu1 + 256*128;  C = g_U1; M = 4096; }

    int row0 = blockIdx.x * 128;
    if (row0 >= M) return;

    __shared__ float sA[16][128];
    __shared__ float sB[16][128];

    int tid = threadIdx.x;
    int tx = tid & 15, ty = tid >> 4;

    ull acc2[8][4];
    #pragma unroll
    for (int i = 0; i < 8; i++)
        #pragma unroll
        for (int j = 0; j < 4; j++) acc2[i][j] = 0ull;

    for (int k0 = 0; k0 < 256; k0 += 16) {
        #pragma unroll
        for (int i = 0; i < 2; i++) {
            int idx = tid * 2 + i;
            int r  = idx >> 2;
            int c4 = (idx & 3) * 4;
            float4 v = *(const float4*)(A + (size_t)(row0 + r) * 256 + k0 + c4);
            sA[c4+0][r] = v.x; sA[c4+1][r] = v.y; sA[c4+2][r] = v.z; sA[c4+3][r] = v.w;
        }
        #pragma unroll
        for (int i = 0; i < 2; i++) {
            int idx = tid * 2 + i;
            int r  = idx >> 5;
            int c4 = (idx & 31) * 4;
            *(float4*)&sB[r][c4] = *(const float4*)(W + (size_t)(k0 + r) * 128 + c4);
        }
        __syncthreads();
        #pragma unroll
        for (int k = 0; k < 16; k++) {
            float4 a0 = *(const float4*)&sA[k][ty*8];
            float4 a1 = *(const float4*)&sA[k][ty*8 + 4];
            float4 b0 = *(const float4*)&sB[k][tx*8];
            float4 b1 = *(const float4*)&sB[k][tx*8 + 4];
            ull bp[4];
            bp[0] = pk2(b0.x, b0.y); bp[1] = pk2(b0.z, b0.w);
            bp[2] = pk2(b1.x, b1.y); bp[3] = pk2(b1.z, b1.w);
            float av[8] = {a0.x, a0.y, a0.z, a0.w, a1.x, a1.y, a1.z, a1.w};
            #pragma unroll
            for (int i = 0; i < 8; i++) {
                ull ap = pk2(av[i], av[i]);
                #pragma unroll
                for (int j = 0; j < 4; j++) fma2(acc2[i][j], ap, bp[j]);
            }
        }
        __syncthreads();
    }
    #pragma unroll
    for (int i = 0; i < 8; i++) {
        int r = row0 + ty*8 + i;
        float c[8];
        #pragma unroll
        for (int j = 0; j < 4; j++) upk2(acc2[i][j], c[2*j], c[2*j+1]);
        *(float4*)(C + (size_t)r * 128 + tx*8    ) = make_float4(c[0],c[1],c[2],c[3]);
        *(float4*)(C + (size_t)r * 128 + tx*8 + 4) = make_float4(c[4],c[5],c[6],c[7]);
    }
}

// ---------------- unary energies (h-pair packed, exact relu trick) --------
__global__ __launch_bounds__(256) void ue_kernel(
    const float* __restrict__ bu1, const float* __restrict__ Wu2,
    const float* __restrict__ bu2)
{
    int b = blockIdx.x;
    int mbase = blockIdx.y * 32;
    __shared__ ull sU1p[64*65];       // [hp][n], stride 65 (odd -> conflict-free)
    __shared__ float redbuf[8];
    int tid = threadIdx.x;
    int hp = tid & 63, ms = tid >> 6;

    for (int i = tid; i < 64*64; i += 256) {
        int n = i >> 6, p = i & 63;
        float2 v = *(const float2*)(g_U1 + (size_t)b*64*128 + n*128 + 2*p);
        sU1p[p*65 + n] = pk2(v.x + bu1[2*p], v.y + bu1[2*p+1]);
    }
    float w0 = Wu2[2*hp], w1 = Wu2[2*hp+1];
    float b2 = bu2[0];
    __syncthreads();

    for (int it = 0; it < 8; it++) {
        int m = mbase + it*4 + ms;
        float2 u0 = *(const float2*)(g_U0 + ((size_t)b*128 + m)*128 + 2*hp);
        ull up = pk2(u0.x, u0.y);
        ull acc = 0ull;
        #pragma unroll 8
        for (int n = 0; n < 64; n++) {
            ull s = add2(up, sU1p[hp*65 + n]);
            acc = add2(acc, add2(s, s & ABS2));   // += 2*relu
        }
        float lo, hi; upk2(acc, lo, hi);
        float v = lo*w0 + hi*w1;
        #pragma unroll
        for (int off = 16; off; off >>= 1) v += __shfl_down_sync(0xffffffffu, v, off);
        if ((tid & 31) == 0) redbuf[tid >> 5] = v;
        __syncthreads();
        if (hp == 0) {
            float t = redbuf[2*ms] + redbuf[2*ms+1];
            g_ue0[b*128 + m] = t * (0.5f/64.f) + b2;
        }
        __syncthreads();
    }
}

// ---------------- level-0 pair scores (h-pair packed) ----------------------
__global__ __launch_bounds__(256) void score0_kernel(
    const float* __restrict__ bp1, const float* __restrict__ Wp2,
    const float* __restrict__ bp2)
{
    int bn = blockIdx.y;
    int m0off = blockIdx.x * 32;
    extern __shared__ ull smu[];
    ull* sH0p = smu;                 // [hp][m0] 64 x 33
    ull* sH1p = sH0p + 64*33;        // [hp][m1] 64 x 129
    ull* sw2h = sH1p + 64*129;       // 64 (0.5*w pairs)
    float* sb0 = (float*)(sw2h + 64);// 32
    float* sb1 = sb0 + 32;           // 128

    const float* h0 = g_P + (size_t)(2*bn  )*128*128 + (size_t)m0off*128;
    const float* h1 = g_Q + (size_t)(2*bn+1)*128*128;
    int tid = threadIdx.x;

    for (int i = tid; i < 32*64; i += 256) {
        int m = i >> 6, hp = i & 63;
        float2 v = *(const float2*)(h0 + m*128 + 2*hp);
        sH0p[hp*33 + m] = pk2(v.x, v.y);
    }
    for (int i = tid; i < 128*64; i += 256) {
        int m = i >> 6, hp = i & 63;
        float2 v = *(const float2*)(h1 + m*128 + 2*hp);
        sH1p[hp*129 + m] = pk2(v.x + bp1[2*hp], v.y + bp1[2*hp+1]);
    }
    if (tid < 64) sw2h[tid] = pk2(0.5f*Wp2[2*tid], 0.5f*Wp2[2*tid+1]);
    float b2 = bp2[0];
    if (tid < 32)  sb0[tid] = g_ue0[(2*bn)*128 + m0off + tid] - b2;
    if (tid < 128) sb1[tid] = g_ue0[(2*bn+1)*128 + tid];
    __syncthreads();

    int i0 = tid >> 5;   // warp id: m0 cells {i0+8c}, broadcast loads
    int jl = tid & 31;   // lane: m1 cells {jl+32c}, conflict-free loads
    ull acc[4][4];
    #pragma unroll
    for (int i = 0; i < 4; i++)
        #pragma unroll
        for (int j = 0; j < 4; j++) acc[i][j] = 0ull;

    for (int hp = 0; hp < 64; hp++) {
        ull wp = sw2h[hp];
        ull A[4], B[4];
        #pragma unroll
        for (int c = 0; c < 4; c++) A[c] = sH0p[hp*33 + i0 + 8*c];
        #pragma unroll
        for (int c = 0; c < 4; c++) B[c] = sH1p[hp*129 + jl + 32*c];
        #pragma unroll
        for (int i = 0; i < 4; i++)
            #pragma unroll
            for (int j = 0; j < 4; j++) {
                ull s = add2(A[i], B[j]);
                s = add2(s, s & ABS2);          // 2*relu
                fma2(acc[i][j], s, wp);
            }
    }
    float* out = g_tot + (size_t)bn * 16384;
    #pragma unroll
    for (int i = 0; i < 4; i++)
        #pragma unroll
        for (int j = 0; j < 4; j++) {
            float lo, hi; upk2(acc[i][j], lo, hi);
            out[(size_t)(m0off + i0 + 8*i) * 128 + jl + 32*j]
                = sb0[i0 + 8*i] + sb1[jl + 32*j] - (lo + hi);
        }
}

// ---------------- exact top-k helpers (binary search on monotone keys) ----
template<int E, bool STRICT>
__device__ __forceinline__ int blk_count(const unsigned keys[E], unsigned piv,
                                         volatile int* red, int NW)
{
    int tid = threadIdx.x;
    int c = 0;
    #pragma unroll
    for (int e = 0; e < E; e++)
        c += STRICT ? (keys[e] < piv ? 1 : 0) : (keys[e] <= piv ? 1 : 0);
    #pragma unroll
    for (int o = 16; o; o >>= 1) c += __shfl_down_sync(0xffffffffu, c, o);
    __syncthreads();
    if ((tid & 31) == 0) red[tid >> 5] = c;
    __syncthreads();
    int tot = 0;
    for (int i = 0; i < NW; i++) tot += red[i];
    return tot;
}

template<int E>
__device__ void collect_and_sort(const unsigned keys[E], int K, unsigned T, int rem,
    unsigned* selk, int* seli, int* tiebuf, int* redmin,
    int* sortedj, float* sortedv, int* sc)
{
    int tid = threadIdx.x;
    int NT  = blockDim.x;
    if (tid == 0) { sc[0] = 0; sc[1] = 0; }
    __syncthreads();
    #pragma unroll
    for (int e = 0; e < E; e++) {
        unsigned k = keys[e]; int idx = tid + e*NT;
        if (k < T)      { int p = atomicAdd(&sc[0], 1); selk[p] = k; seli[p] = idx; }
        else if (k == T){ int p = atomicAdd(&sc[1], 1); if (p < 512) tiebuf[p] = idx; }
    }
    __syncthreads();
    int c = sc[0];
    int tn = min(sc[1], 512);
    for (int r = 0; r < rem; r++) {
        int bi = 0x7fffffff;
        for (int j = tid; j < tn; j += NT) bi = min(bi, tiebuf[j]);
        redmin[tid] = bi;
        __syncthreads();
        for (int s = NT >> 1; s; s >>= 1) {
            if (tid < s) redmin[tid] = min(redmin[tid], redmin[tid + s]);
            __syncthreads();
        }
        int wv = redmin[0];
        __syncthreads();
        if (tid == 0) { selk[c + r] = T; seli[c + r] = wv; }
        for (int j = tid; j < tn; j += NT)
            if (tiebuf[j] == wv) tiebuf[j] = 0x7fffffff;
        __syncthreads();
    }
    if (tid < K) {   // rank-sort: (key asc, index asc) == jax.lax.top_k order
        unsigned k = selk[tid]; int idx = seli[tid];
        int rank = 0;
        for (int j = 0; j < K; j++) {
            unsigned kj = selk[j]; int ij = seli[j];
            if (kj < k || (kj == k && ij < idx)) rank++;
        }
        sortedj[rank] = idx;
        unsigned b = (k & 0x80000000u) ? (k & 0x7FFFFFFFu) : ~k;
        sortedv[rank] = __uint_as_float(b);
    }
    __syncthreads();
}

// ---------------- level-0 top-64 ----------------
__global__ __launch_bounds__(512) void topk0_kernel()
{
    __shared__ unsigned selk[64];
    __shared__ int seli[64], tiebuf[512], redmin[512], sortedj[64];
    __shared__ float sortedv[64];
    __shared__ int subnew[128];
    __shared__ int red[16], sc[2];

    int tid = threadIdx.x, bn = blockIdx.x;
    unsigned keys[32];
    const float* tsrc = g_tot + (size_t)bn * 16384;
    #pragma unroll
    for (int e = 0; e < 32; e++) {
        unsigned b = __float_as_uint(tsrc[tid + 512*e]);
        keys[e] = (b & 0x80000000u) ? ~b : (b | 0x80000000u);
    }

    unsigned lo = 0u, hi = 0xFFFFFFFFu;
    while (lo < hi) {
        unsigned mid = lo + ((hi - lo) >> 1);
        int cnt = blk_count<32,false>(keys, mid, red, 16);
        if (cnt >= 64) hi = mid; else lo = mid + 1;
    }
    unsigned T = lo;
    int cntLess = blk_count<32,true>(keys, T, red, 16);
    int rem = 64 - cntLess;

    collect_and_sort<32>(keys, 64, T, rem, selk, seli, tiebuf, redmin, sortedj, sortedv, sc);

    if (tid < 64) {
        int j = sortedj[tid]; int m0 = j >> 7, m1 = j & 127;
        float uen = g_ue0[(2*bn)*128 + m0] + g_ue0[(2*bn+1)*128 + m1];
        g_ueA[bn*64 + tid] = uen;
        g_peA[bn*64 + tid] = sortedv[tid] - uen;
        subnew[tid*2] = m0; subnew[tid*2 + 1] = m1;
        g_subA[(bn*64 + tid)*2    ] = m0;
        g_subA[(bn*64 + tid)*2 + 1] = m1;
    }
    __syncthreads();
    const float* X = (bn & 1) ? g_Q : g_P;
    for (int idx = tid; idx < 64*128; idx += 512) {
        int r = idx >> 7, h = idx & 127;
        float s = X[((size_t)(bn*2    )*128 + subnew[r*2    ])*128 + h]
                + X[((size_t)(bn*2 + 1)*128 + subnew[r*2 + 1])*128 + h];
        g_H[((size_t)bn*64 + r)*128 + h] = s * 0.5f;
    }
}

// ---------------- fused score+top-k for levels 1 & 2 ----------------------
template<int LVL>
__global__ __launch_bounds__(512) void level_kernel(
    const float* __restrict__ bp1, const float* __restrict__ Wp2,
    const float* __restrict__ bp2, float* __restrict__ d_out)
{
    constexpr int K    = (LVL == 1) ? 64 : 1;
    constexpr int S_in = (LVL == 1) ? 2 : 4;
    constexpr int S2   = 2 * S_in;
    const float* ue_in = (LVL == 1) ? g_ueA : g_ueB;
    const float* pe_in = (LVL == 1) ? g_peA : g_peB;
    const int*  sub_in = (LVL == 1) ? g_subA : g_subB;
    float* pe_out      = (LVL == 1) ? g_peB : g_peA;
    float* ue_out      = (LVL == 1) ? g_ueB : g_ueA;
    int*  sub_out      = (LVL == 1) ? g_subB : g_subA;

    extern __shared__ ull smu[];
    ull* sH0p = smu;                    // 64 x 65
    ull* sH1p = sH0p + 64*65;           // 64 x 65
    ull* sw2h = sH1p + 64*65;           // 64
    float* sb0 = (float*)(sw2h + 64);   // 64
    float* sb1 = sb0 + 64;              // 64
    unsigned* selk = (unsigned*)(sb1 + 64); // 64
    int* seli    = (int*)(selk + 64);   // 64
    int* tiebuf  = seli + 64;           // 512
    int* redmin  = tiebuf + 512;        // 512
    int* sortedj = redmin + 512;        // 64
    float* sortedv = (float*)(sortedj + 64); // 64
    int* subnew  = (int*)(sortedv + 64);// 512
    int* red     = subnew + 512;        // 16
    int* sc      = red + 16;            // 2

    int tid = threadIdx.x, bn = blockIdx.x;
    const float* h0 = g_H + (size_t)(2*bn    )*64*128;
    const float* h1 = g_H + (size_t)(2*bn + 1)*64*128;

    for (int i = tid; i < 4096; i += 512) {
        int m = i >> 6, hp = i & 63;
        float2 v0 = *(const float2*)(h0 + m*128 + 2*hp);
        float2 v1 = *(const float2*)(h1 + m*128 + 2*hp);
        sH0p[hp*65 + m] = pk2(v0.x, v0.y);
        sH1p[hp*65 + m] = pk2(v1.x + bp1[2*hp], v1.y + bp1[2*hp+1]);
    }
    if (tid < 64) sw2h[tid] = pk2(0.5f*Wp2[2*tid], 0.5f*Wp2[2*tid+1]);
    float b2 = bp2[0];
    if (tid < 64) sb0[tid] = ue_in[(2*bn)*64 + tid] + pe_in[(2*bn)*64 + tid] - b2;
    else if (tid < 128) {
        int m = tid - 64;
        sb1[m] = ue_in[(2*bn+1)*64 + m] + pe_in[(2*bn+1)*64 + m];
    }
    __syncthreads();

    int m1 = tid & 63;
    int m0b = tid >> 6;
    ull acc[8];
    #pragma unroll
    for (int e = 0; e < 8; e++) acc[e] = 0ull;
    for (int hp = 0; hp < 64; hp++) {
        ull bb = sH1p[hp*65 + m1];
        ull wp = sw2h[hp];
        #pragma unroll
        for (int e = 0; e < 8; e++) {
            ull a = sH0p[hp*65 + m0b + 8*e];
            ull s = add2(a, bb);
            s = add2(s, s & ABS2);
            fma2(acc[e], s, wp);
        }
    }
    unsigned keys[8];
    #pragma unroll
    for (int e = 0; e < 8; e++) {
        float lo_, hi_; upk2(acc[e], lo_, hi_);
        float val = sb0[m0b + 8*e] + sb1[m1] - (lo_ + hi_);
        unsigned b = __float_as_uint(val);
        keys[e] = (b & 0x80000000u) ? ~b : (b | 0x80000000u);
    }

    unsigned lo = 0u, hi = 0xFFFFFFFFu;
    while (lo < hi) {
        unsigned mid = lo + ((hi - lo) >> 1);
        int cnt = blk_count<8,false>(keys, mid, red, 16);
        if (cnt >= K) hi = mid; else lo = mid + 1;
    }
    unsigned T = lo;
    int cntLess = blk_count<8,true>(keys, T, red, 16);
    int rem = K - cntLess;

    collect_and_sort<8>(keys, K, T, rem, selk, seli, tiebuf, redmin, sortedj, sortedv, sc);

    if (tid < K) {
        int j = sortedj[tid]; int m0 = j >> 6, m1s = j & 63;
        float uen = ue_in[(2*bn)*64 + m0] + ue_in[(2*bn+1)*64 + m1s];
        ue_out[bn*K + tid] = uen;
        pe_out[bn*K + tid] = sortedv[tid] - uen;
        for (int s = 0; s < S_in; s++) {
            subnew[tid*S2 + s]        = sub_in[((2*bn)*64 + m0)*S_in + s];
            subnew[tid*S2 + S_in + s] = sub_in[((2*bn+1)*64 + m1s)*S_in + s];
        }
        for (int s = 0; s < S2; s++)
            sub_out[(bn*K + tid)*S2 + s] = subnew[tid*S2 + s];
    }
    __syncthreads();

    if (LVL == 1) {
        const float* X = (bn & 1) ? g_Q : g_P;
        const float inv = 1.f / (float)S2;
        for (int idx = tid; idx < K*128; idx += 512) {
            int r = idx >> 7, h = idx & 127;
            float s = 0.f;
            for (int s2i = 0; s2i < S2; s2i++)
                s += X[((size_t)(bn*S2 + s2i)*128 + subnew[r*S2 + s2i])*128 + h];
            g_H[((size_t)bn*K + r)*128 + h] = s * inv;
        }
    } else {
        if (tid < S2) d_out[bn*S2 + tid] = (float)subnew[tid];
    }
}

// ---------------- is_target ----------------
__global__ __launch_bounds__(256) void istarget_kernel(
    const int* __restrict__ pos_classes, const int* __restrict__ target,
    float* __restrict__ out)
{
    int i = blockIdx.x * 256 + threadIdx.x;
    if (i < 8192) {
        int b = i >> 10;
        out[64 + i] = (pos_classes[i] == target[b]) ? 1.f : 0.f;
    }
}

// ---------------- launch ----------------
extern "C" void kernel_launch(void* const* d_in, const int* in_sizes, int n_in,
                              void* d_out, int out_size)
{
    const float* pos  = (const float*)d_in[0];
    const float* neg  = (const float*)d_in[1];
    const int*   pcls = (const int*)  d_in[2];
    const int*   tcls = (const int*)  d_in[3];
    const float* Wp1  = (const float*)d_in[4];
    const float* bp1  = (const float*)d_in[5];
    const float* Wp2  = (const float*)d_in[6];
    const float* bp2  = (const float*)d_in[7];
    const float* Wu1  = (const float*)d_in[8];
    const float* bu1  = (const float*)d_in[9];
    const float* Wu2  = (const float*)d_in[10];
    const float* bu2  = (const float*)d_in[11];
    float* out = (float*)d_out;

    size_t smS0 = (size_t)(64*33 + 64*129 + 64) * 8 + (size_t)(32 + 128) * 4;   // 84,096
    size_t smL  = (size_t)(64*65*2 + 64) * 8
                + (size_t)(64 + 64 + 64 + 64 + 512 + 512 + 64 + 64 + 512 + 16 + 2) * 4; // ~74.8KB

    cudaFuncSetAttribute(score0_kernel,  cudaFuncAttributeMaxDynamicSharedMemorySize, (int)smS0);
    cudaFuncSetAttribute(level_kernel<1>, cudaFuncAttributeMaxDynamicSharedMemorySize, (int)smL);
    cudaFuncSetAttribute(level_kernel<2>, cudaFuncAttributeMaxDynamicSharedMemorySize, (int)smL);

    gemm_all<<<dim3(64, 4), 256>>>(pos, neg, Wp1, Wu1);
    ue_kernel<<<dim3(64, 4), 256>>>(bu1, Wu2, bu2);
    score0_kernel<<<dim3(4, 32), 256, smS0>>>(bp1, Wp2, bp2);
    topk0_kernel<<<32, 512>>>();
    level_kernel<1><<<16, 512, smL>>>(bp1, Wp2, bp2, out);
    level_kernel<2><<<8, 512, smL>>>(bp1, Wp2, bp2, out);
    istarget_kernel<<<32, 256>>>(pcls, tcls, out);
}

// round 4
// speedup vs baseline: 1.7643x; 1.2018x over previous
#include <cuda_runtime.h>
#include <math.h>

typedef unsigned long long ull;
#define ABS2 0x7FFFFFFF7FFFFFFFULL

// ---------------- scratch (device globals; no allocations) ----------------
__device__ float g_P [8192*128];
__device__ float g_Q [8192*128];
__device__ float g_U0[8192*128];
__device__ float g_U1[4096*128];
__device__ float g_ue0[64*128];
__device__ ull   g_cand[32*4*64];  // per-quadrant top-64 candidates (packed key|idx)
__device__ float g_H  [32*64*128];
__device__ float g_H2 [16*64*128];
__device__ float g_peA[32*64];
__device__ float g_ueA[32*64];
__device__ float g_peB[16*64];
__device__ float g_ueB[16*64];
__device__ int   g_subA[32*64*2];
__device__ int   g_subB[16*64*4];

// ---------------- f32x2 packed helpers ----------------
__device__ __forceinline__ ull pk2(float x, float y) {
    ull r; asm("mov.b64 %0, {%1,%2};" : "=l"(r) : "f"(x), "f"(y)); return r;
}
__device__ __forceinline__ void upk2(ull v, float &lo, float &hi) {
    asm("mov.b64 {%0,%1}, %2;" : "=f"(lo), "=f"(hi) : "l"(v));
}
__device__ __forceinline__ ull add2(ull a, ull b) {
    ull r; asm("add.rn.f32x2 %0, %1, %2;" : "=l"(r) : "l"(a), "l"(b)); return r;
}
__device__ __forceinline__ void fma2(ull &d, ull a, ull b) {
    asm("fma.rn.f32x2 %0, %1, %2, %0;" : "+l"(d) : "l"(a), "l"(b));
}

// monotone float->u32 key (unsigned asc == float asc)
__device__ __forceinline__ unsigned fkey(float v) {
    unsigned b = __float_as_uint(v);
    return (b & 0x80000000u) ? ~b : (b | 0x80000000u);
}
__device__ __forceinline__ float unfkey(unsigned k) {
    unsigned b = (k & 0x80000000u) ? (k & 0x7FFFFFFFu) : ~k;
    return __uint_as_float(b);
}
__device__ __forceinline__ ull umin64(ull a, ull b) { return a < b ? a : b; }

// ---------------- SGEMM: C[M,128] = A[M,256] @ W[256,128] (f32x2) ----------
__global__ __launch_bounds__(256) void gemm_all(
    const float* __restrict__ pos, const float* __restrict__ neg,
    const float* __restrict__ Wp1, const float* __restrict__ Wu1)
{
    const float* A; const float* W; float* C; int M;
    int g = blockIdx.y;
    if      (g == 0) { A = pos; W = Wp1;            C = g_P;  M = 8192; }
    else if (g == 1) { A = pos; W = Wp1 + 256*128;  C = g_Q;  M = 8192; }
    else if (g == 2) { A = pos; W = Wu1;            C = g_U0; M = 8192; }
    else             { A = neg; W = Wu1 + 256*128;  C = g_U1; M = 4096; }

    int row0 = blockIdx.x * 128;
    if (row0 >= M) return;

    __shared__ float sA[16][128];
    __shared__ float sB[16][128];

    int tid = threadIdx.x;
    int tx = tid & 15, ty = tid >> 4;

    ull acc2[8][4];
    #pragma unroll
    for (int i = 0; i < 8; i++)
        #pragma unroll
        for (int j = 0; j < 4; j++) acc2[i][j] = 0ull;

    for (int k0 = 0; k0 < 256; k0 += 16) {
        #pragma unroll
        for (int i = 0; i < 2; i++) {
            int idx = tid * 2 + i;
            int r  = idx >> 2;
            int c4 = (idx & 3) * 4;
            float4 v = *(const float4*)(A + (size_t)(row0 + r) * 256 + k0 + c4);
            sA[c4+0][r] = v.x; sA[c4+1][r] = v.y; sA[c4+2][r] = v.z; sA[c4+3][r] = v.w;
        }
        #pragma unroll
        for (int i = 0; i < 2; i++) {
            int idx = tid * 2 + i;
            int r  = idx >> 5;
            int c4 = (idx & 31) * 4;
            *(float4*)&sB[r][c4] = *(const float4*)(W + (size_t)(k0 + r) * 128 + c4);
        }
        __syncthreads();
        #pragma unroll
        for (int k = 0; k < 16; k++) {
            float4 a0 = *(const float4*)&sA[k][ty*8];
            float4 a1 = *(const float4*)&sA[k][ty*8 + 4];
            float4 b0 = *(const float4*)&sB[k][tx*8];
            float4 b1 = *(const float4*)&sB[k][tx*8 + 4];
            ull bp[4];
            bp[0] = pk2(b0.x, b0.y); bp[1] = pk2(b0.z, b0.w);
            bp[2] = pk2(b1.x, b1.y); bp[3] = pk2(b1.z, b1.w);
            float av[8] = {a0.x, a0.y, a0.z, a0.w, a1.x, a1.y, a1.z, a1.w};
            #pragma unroll
            for (int i = 0; i < 8; i++) {
                ull ap = pk2(av[i], av[i]);
                #pragma unroll
                for (int j = 0; j < 4; j++) fma2(acc2[i][j], ap, bp[j]);
            }
        }
        __syncthreads();
    }
    #pragma unroll
    for (int i = 0; i < 8; i++) {
        int r = row0 + ty*8 + i;
        float c[8];
        #pragma unroll
        for (int j = 0; j < 4; j++) upk2(acc2[i][j], c[2*j], c[2*j+1]);
        *(float4*)(C + (size_t)r * 128 + tx*8    ) = make_float4(c[0],c[1],c[2],c[3]);
        *(float4*)(C + (size_t)r * 128 + tx*8 + 4) = make_float4(c[4],c[5],c[6],c[7]);
    }
}

// ---------------- unary energies (h-pair packed, exact relu trick) --------
__global__ __launch_bounds__(256) void ue_kernel(
    const float* __restrict__ bu1, const float* __restrict__ Wu2,
    const float* __restrict__ bu2)
{
    int b = blockIdx.x;
    int mbase = blockIdx.y * 32;
    __shared__ ull sU1p[64*65];
    __shared__ float redbuf[8];
    int tid = threadIdx.x;
    int hp = tid & 63, ms = tid >> 6;

    for (int i = tid; i < 64*64; i += 256) {
        int n = i >> 6, p = i & 63;
        float2 v = *(const float2*)(g_U1 + (size_t)b*64*128 + n*128 + 2*p);
        sU1p[p*65 + n] = pk2(v.x + bu1[2*p], v.y + bu1[2*p+1]);
    }
    float w0 = Wu2[2*hp], w1 = Wu2[2*hp+1];
    float b2 = bu2[0];
    __syncthreads();

    for (int it = 0; it < 8; it++) {
        int m = mbase + it*4 + ms;
        float2 u0 = *(const float2*)(g_U0 + ((size_t)b*128 + m)*128 + 2*hp);
        ull up = pk2(u0.x, u0.y);
        ull acc = 0ull;
        #pragma unroll 8
        for (int n = 0; n < 64; n++) {
            ull s = add2(up, sU1p[hp*65 + n]);
            acc = add2(acc, add2(s, s & ABS2));   // += 2*relu
        }
        float lo, hi; upk2(acc, lo, hi);
        float v = lo*w0 + hi*w1;
        #pragma unroll
        for (int off = 16; off; off >>= 1) v += __shfl_down_sync(0xffffffffu, v, off);
        if ((tid & 31) == 0) redbuf[tid >> 5] = v;
        __syncthreads();
        if (hp == 0) {
            float t = redbuf[2*ms] + redbuf[2*ms+1];
            g_ue0[b*128 + m] = t * (0.5f/64.f) + b2;
        }
        __syncthreads();
    }
}

// ---------------- histogram radix threshold on packed (key32<<32|idx) -----
// Finds K-th smallest key32 (T) and rem = # of key==T elements to take.
template<int E>
__device__ void radix_thresh(const ull (&pk)[E], int K, int* hist, int NW,
                             unsigned &T, int &rem)
{
    __shared__ int wred[8];
    __shared__ int s_bin, s_prev, s_rem;
    __shared__ unsigned s_pref;
    int tid = threadIdx.x, NT = blockDim.x;
    int wid = tid >> 5, lane = tid & 31;
    if (tid == 0) { s_pref = 0u; s_rem = K; }
    __syncthreads();
    #pragma unroll
    for (int pass = 0; pass < 4; pass++) {
        int shift = 24 - 8*pass;
        for (int i = tid; i < NW*256; i += NT) hist[i] = 0;
        __syncthreads();
        unsigned pmask = pass ? (0xFFFFFFFFu << (shift + 8)) : 0u;
        unsigned pref = s_pref;
        #pragma unroll
        for (int e = 0; e < E; e++) {
            unsigned k = (unsigned)(pk[e] >> 32);
            if ((k & pmask) == pref)
                atomicAdd(&hist[wid*256 + ((k >> shift) & 255)], 1);
        }
        __syncthreads();
        int tot = 0, v = 0;
        if (tid < 256) {
            for (int w = 0; w < NW; w++) tot += hist[w*256 + tid];
            v = tot;
            #pragma unroll
            for (int d = 1; d < 32; d <<= 1) {
                int u = __shfl_up_sync(0xffffffffu, v, d);
                if (lane >= d) v += u;
            }
            if (lane == 31) wred[wid] = v;
        }
        __syncthreads();
        if (tid == 0) {
            int acc = 0;
            for (int w = 0; w < 8; w++) { int t = wred[w]; wred[w] = acc; acc += t; }
        }
        __syncthreads();
        if (tid < 256) {
            v += wred[wid];
            int rm = s_rem;
            if (v >= rm && (v - tot) < rm) { s_bin = tid; s_prev = v - tot; }
        }
        __syncthreads();
        if (tid == 0) { s_rem -= s_prev; s_pref = pref | ((unsigned)s_bin << shift); }
        __syncthreads();
    }
    T = s_pref;
    rem = s_rem;
}

// collect exactly K winners into cand[] (unordered): all key<T plus rem
// smallest-index key==T. Mutates pk (marks taken ties).
template<int E>
__device__ void collect_packed(ull (&pk)[E], int K, unsigned T, int rem, ull* cand)
{
    __shared__ ull wmin[16];
    __shared__ ull s_minv;
    __shared__ int s_cnt;
    int tid = threadIdx.x, NT = blockDim.x, NW = NT >> 5;
    if (tid == 0) s_cnt = 0;
    __syncthreads();
    #pragma unroll
    for (int e = 0; e < E; e++) {
        if ((unsigned)(pk[e] >> 32) < T) {
            int p = atomicAdd(&s_cnt, 1);
            cand[p] = pk[e];
        }
    }
    __syncthreads();
    int base = K - rem;
    for (int r = 0; r < rem; r++) {
        ull m = ~0ull;
        #pragma unroll
        for (int e = 0; e < E; e++)
            if ((unsigned)(pk[e] >> 32) == T) m = umin64(m, pk[e]);
        #pragma unroll
        for (int o = 16; o; o >>= 1) m = umin64(m, __shfl_down_sync(0xffffffffu, m, o));
        if ((tid & 31) == 0) wmin[tid >> 5] = m;
        __syncthreads();
        if (tid == 0) {
            ull mm = ~0ull;
            for (int w = 0; w < NW; w++) mm = umin64(mm, wmin[w]);
            s_minv = mm;
            cand[base + r] = mm;
        }
        __syncthreads();
        ull mm = s_minv;
        #pragma unroll
        for (int e = 0; e < E; e++)
            if (pk[e] == mm) pk[e] = ~0ull;   // mark taken
    }
    __syncthreads();
}

// ---------------- level-0: pair scores + per-quadrant exact top-64 --------
__global__ __launch_bounds__(256) void score0_kernel(
    const float* __restrict__ bp1, const float* __restrict__ Wp2,
    const float* __restrict__ bp2)
{
    int bn = blockIdx.y;
    int quad = blockIdx.x;
    int m0off = quad * 32;
    extern __shared__ ull smu[];
    ull* sH0p = smu;                 // [hp][m0] 64 x 33
    ull* sH1p = sH0p + 64*33;        // [hp][m1] 64 x 129
    ull* sw2h = sH1p + 64*129;       // 64
    ull* cand = sw2h + 64;           // 64
    float* sb0 = (float*)(cand + 64);// 32
    float* sb1 = sb0 + 32;           // 128
    int* hist  = (int*)(sb1 + 128);  // 8*256

    const float* h0 = g_P + (size_t)(2*bn  )*128*128 + (size_t)m0off*128;
    const float* h1 = g_Q + (size_t)(2*bn+1)*128*128;
    int tid = threadIdx.x;

    for (int i = tid; i < 32*64; i += 256) {
        int m = i >> 6, hp = i & 63;
        float2 v = *(const float2*)(h0 + m*128 + 2*hp);
        sH0p[hp*33 + m] = pk2(v.x, v.y);
    }
    for (int i = tid; i < 128*64; i += 256) {
        int m = i >> 6, hp = i & 63;
        float2 v = *(const float2*)(h1 + m*128 + 2*hp);
        sH1p[hp*129 + m] = pk2(v.x + bp1[2*hp], v.y + bp1[2*hp+1]);
    }
    if (tid < 64) sw2h[tid] = pk2(0.5f*Wp2[2*tid], 0.5f*Wp2[2*tid+1]);
    float b2 = bp2[0];
    if (tid < 32)  sb0[tid] = g_ue0[(2*bn)*128 + m0off + tid] - b2;
    if (tid < 128) sb1[tid] = g_ue0[(2*bn+1)*128 + tid];
    __syncthreads();

    int i0 = tid >> 5;
    int jl = tid & 31;
    ull acc[4][4];
    #pragma unroll
    for (int i = 0; i < 4; i++)
        #pragma unroll
        for (int j = 0; j < 4; j++) acc[i][j] = 0ull;

    for (int hp = 0; hp < 64; hp++) {
        ull wp = sw2h[hp];
        ull A[4], B[4];
        #pragma unroll
        for (int c = 0; c < 4; c++) A[c] = sH0p[hp*33 + i0 + 8*c];
        #pragma unroll
        for (int c = 0; c < 4; c++) B[c] = sH1p[hp*129 + jl + 32*c];
        #pragma unroll
        for (int i = 0; i < 4; i++)
            #pragma unroll
            for (int j = 0; j < 4; j++) {
                ull s = add2(A[i], B[j]);
                s = add2(s, s & ABS2);
                fma2(acc[i][j], s, wp);
            }
    }

    ull pk[16];
    #pragma unroll
    for (int i = 0; i < 4; i++)
        #pragma unroll
        for (int j = 0; j < 4; j++) {
            float lo, hi; upk2(acc[i][j], lo, hi);
            float val = sb0[i0 + 8*i] + sb1[jl + 32*j] - (lo + hi);
            int gidx = (m0off + i0 + 8*i) * 128 + (jl + 32*j);
            pk[i*4+j] = ((ull)fkey(val) << 32) | (unsigned)gidx;
        }

    unsigned T; int rem;
    radix_thresh<16>(pk, 64, hist, 8, T, rem);
    collect_packed<16>(pk, 64, T, rem, cand);

    if (tid < 64) g_cand[(bn*4 + quad)*64 + tid] = cand[tid];
}

// ---------------- level-0 final merge: 256 candidates -> exact top-64 -----
__global__ __launch_bounds__(256) void final0_kernel()
{
    __shared__ ull scand[256];
    __shared__ int sortedj[64];
    __shared__ float sortedv[64];
    __shared__ int subnew[128];
    int tid = threadIdx.x, bn = blockIdx.x;

    ull c = g_cand[bn*256 + tid];
    scand[tid] = c;
    __syncthreads();
    int rank = 0;
    for (int i = 0; i < 256; i++) rank += (scand[i] < c) ? 1 : 0;
    if (rank < 64) {
        sortedj[rank] = (int)(c & 0xFFFFFFFFu);
        sortedv[rank] = unfkey((unsigned)(c >> 32));
    }
    __syncthreads();

    if (tid < 64) {
        int j = sortedj[tid]; int m0 = j >> 7, m1 = j & 127;
        float uen = g_ue0[(2*bn)*128 + m0] + g_ue0[(2*bn+1)*128 + m1];
        g_ueA[bn*64 + tid] = uen;
        g_peA[bn*64 + tid] = sortedv[tid] - uen;
        subnew[tid*2] = m0; subnew[tid*2 + 1] = m1;
        g_subA[(bn*64 + tid)*2    ] = m0;
        g_subA[(bn*64 + tid)*2 + 1] = m1;
    }
    __syncthreads();

    const float* X = (bn & 1) ? g_Q : g_P;
    for (int idx = tid; idx < 64*128; idx += 256) {
        int r = idx >> 7, h = idx & 127;
        float s = X[((size_t)(bn*2    )*128 + subnew[r*2    ])*128 + h]
                + X[((size_t)(bn*2 + 1)*128 + subnew[r*2 + 1])*128 + h];
        g_H[((size_t)bn*64 + r)*128 + h] = s * 0.5f;
    }
}

// ---------------- fused score+select for levels 1 & 2 ---------------------
template<int LVL>
__global__ __launch_bounds__(512) void level_kernel(
    const float* __restrict__ bp1, const float* __restrict__ Wp2,
    const float* __restrict__ bp2, float* __restrict__ d_out)
{
    extern __shared__ ull smu[];
    ull* sH0p = smu;                    // 64 x 65
    ull* sH1p = sH0p + 64*65;           // 64 x 65
    ull* sw2h = sH1p + 64*65;           // 64
    ull* cand = sw2h + 64;              // 64
    float* sb0 = (float*)(cand + 64);   // 64
    float* sb1 = sb0 + 64;              // 64
    int* hist  = (int*)(sb1 + 64);      // 16*256

    __shared__ int sortedj[64];
    __shared__ float sortedv[64];
    __shared__ int subnew[512];
    __shared__ ull awmin[16];
    __shared__ ull s_win;

    const float* ue_in = (LVL == 1) ? g_ueA : g_ueB;
    const float* pe_in = (LVL == 1) ? g_peA : g_peB;
    const int*  sub_in = (LVL == 1) ? g_subA : g_subB;
    const float* Hin   = (LVL == 1) ? g_H : g_H2;

    int tid = threadIdx.x, bn = blockIdx.x;
    const float* h0 = Hin + (size_t)(2*bn    )*64*128;
    const float* h1 = Hin + (size_t)(2*bn + 1)*64*128;

    for (int i = tid; i < 4096; i += 512) {
        int m = i >> 6, hp = i & 63;
        float2 v0 = *(const float2*)(h0 + m*128 + 2*hp);
        float2 v1 = *(const float2*)(h1 + m*128 + 2*hp);
        sH0p[hp*65 + m] = pk2(v0.x, v0.y);
        sH1p[hp*65 + m] = pk2(v1.x + bp1[2*hp], v1.y + bp1[2*hp+1]);
    }
    if (tid < 64) sw2h[tid] = pk2(0.5f*Wp2[2*tid], 0.5f*Wp2[2*tid+1]);
    float b2 = bp2[0];
    if (tid < 64) sb0[tid] = ue_in[(2*bn)*64 + tid] + pe_in[(2*bn)*64 + tid] - b2;
    else if (tid < 128) {
        int m = tid - 64;
        sb1[m] = ue_in[(2*bn+1)*64 + m] + pe_in[(2*bn+1)*64 + m];
    }
    __syncthreads();

    int m1 = tid & 63;
    int m0b = tid >> 6;
    ull acc[8];
    #pragma unroll
    for (int e = 0; e < 8; e++) acc[e] = 0ull;
    for (int hp = 0; hp < 64; hp++) {
        ull bb = sH1p[hp*65 + m1];
        ull wp = sw2h[hp];
        #pragma unroll
        for (int e = 0; e < 8; e++) {
            ull a = sH0p[hp*65 + m0b + 8*e];
            ull s = add2(a, bb);
            s = add2(s, s & ABS2);
            fma2(acc[e], s, wp);
        }
    }
    ull pk[8];
    #pragma unroll
    for (int e = 0; e < 8; e++) {
        float lo_, hi_; upk2(acc[e], lo_, hi_);
        float val = sb0[m0b + 8*e] + sb1[m1] - (lo_ + hi_);
        pk[e] = ((ull)fkey(val) << 32) | (unsigned)(tid + 512*e);
    }

    if (LVL == 2) {
        // K=1: plain block argmin on packed (val, idx)
        ull m = ~0ull;
        #pragma unroll
        for (int e = 0; e < 8; e++) m = umin64(m, pk[e]);
        #pragma unroll
        for (int o = 16; o; o >>= 1) m = umin64(m, __shfl_down_sync(0xffffffffu, m, o));
        if ((tid & 31) == 0) awmin[tid >> 5] = m;
        __syncthreads();
        if (tid == 0) {
            ull mm = ~0ull;
            for (int w = 0; w < 16; w++) mm = umin64(mm, awmin[w]);
            s_win = mm;
        }
        __syncthreads();
        if (tid < 8) {
            int j = (int)(s_win & 0xFFFFFFFFu);
            int m0 = j >> 6, m1s = j & 63;
            int v = (tid < 4) ? sub_in[((2*bn)*64 + m0)*4 + tid]
                              : sub_in[((2*bn+1)*64 + m1s)*4 + (tid - 4)];
            d_out[bn*8 + tid] = (float)v;
        }
        return;
    }

    // LVL == 1: exact top-64
    unsigned T; int rem;
    radix_thresh<8>(pk, 64, hist, 16, T, rem);
    collect_packed<8>(pk, 64, T, rem, cand);

    if (tid < 64) {
        ull c = cand[tid];
        int rank = 0;
        for (int i = 0; i < 64; i++) rank += (cand[i] < c) ? 1 : 0;
        sortedj[rank] = (int)(c & 0xFFFFFFFFu);
        sortedv[rank] = unfkey((unsigned)(c >> 32));
    }
    __syncthreads();

    if (tid < 64) {
        int j = sortedj[tid]; int m0 = j >> 6, m1s = j & 63;
        float uen = ue_in[(2*bn)*64 + m0] + ue_in[(2*bn+1)*64 + m1s];
        g_ueB[bn*64 + tid] = uen;
        g_peB[bn*64 + tid] = sortedv[tid] - uen;
        #pragma unroll
        for (int s = 0; s < 2; s++) {
            subnew[tid*4 + s]     = sub_in[((2*bn)*64 + m0)*2 + s];
            subnew[tid*4 + 2 + s] = sub_in[((2*bn+1)*64 + m1s)*2 + s];
        }
        #pragma unroll
        for (int s = 0; s < 4; s++)
            g_subB[(bn*64 + tid)*4 + s] = subnew[tid*4 + s];
    }
    __syncthreads();

    const float* X = (bn & 1) ? g_Q : g_P;
    for (int idx = tid; idx < 64*128; idx += 512) {
        int r = idx >> 7, h = idx & 127;
        float s = 0.f;
        #pragma unroll
        for (int s2i = 0; s2i < 4; s2i++)
            s += X[((size_t)(bn*4 + s2i)*128 + subnew[r*4 + s2i])*128 + h];
        g_H2[((size_t)bn*64 + r)*128 + h] = s * 0.25f;
    }
}

// ---------------- is_target ----------------
__global__ __launch_bounds__(256) void istarget_kernel(
    const int* __restrict__ pos_classes, const int* __restrict__ target,
    float* __restrict__ out)
{
    int i = blockIdx.x * 256 + threadIdx.x;
    if (i < 8192) {
        int b = i >> 10;
        out[64 + i] = (pos_classes[i] == target[b]) ? 1.f : 0.f;
    }
}

// ---------------- launch ----------------
extern "C" void kernel_launch(void* const* d_in, const int* in_sizes, int n_in,
                              void* d_out, int out_size)
{
    const float* pos  = (const float*)d_in[0];
    const float* neg  = (const float*)d_in[1];
    const int*   pcls = (const int*)  d_in[2];
    const int*   tcls = (const int*)  d_in[3];
    const float* Wp1  = (const float*)d_in[4];
    const float* bp1  = (const float*)d_in[5];
    const float* Wp2  = (const float*)d_in[6];
    const float* bp2  = (const float*)d_in[7];
    const float* Wu1  = (const float*)d_in[8];
    const float* bu1  = (const float*)d_in[9];
    const float* Wu2  = (const float*)d_in[10];
    const float* bu2  = (const float*)d_in[11];
    float* out = (float*)d_out;

    // dynamic smem: score0 = 10496 ull + 160 f + 2048 i  = 92,800 B
    //               level  =  8448 ull + 128 f + 4096 i  = 84,480 B
    size_t smS0 = (size_t)10496*8 + 160*4 + 2048*4;
    size_t smL  = (size_t)8448*8  + 128*4 + 4096*4;

    cudaFuncSetAttribute(score0_kernel,   cudaFuncAttributeMaxDynamicSharedMemorySize, (int)smS0);
    cudaFuncSetAttribute(level_kernel<1>, cudaFuncAttributeMaxDynamicSharedMemorySize, (int)smL);
    cudaFuncSetAttribute(level_kernel<2>, cudaFuncAttributeMaxDynamicSharedMemorySize, (int)smL);

    gemm_all<<<dim3(64, 4), 256>>>(pos, neg, Wp1, Wu1);
    ue_kernel<<<dim3(64, 4), 256>>>(bu1, Wu2, bu2);
    score0_kernel<<<dim3(4, 32), 256, smS0>>>(bp1, Wp2, bp2);
    final0_kernel<<<32, 256>>>();
    level_kernel<1><<<16, 512, smL>>>(bp1, Wp2, bp2, out);
    level_kernel<2><<<8, 512, smL>>>(bp1, Wp2, bp2, out);
    istarget_kernel<<<32, 256>>>(pcls, tcls, out);
}

// round 5
// speedup vs baseline: 1.8794x; 1.0652x over previous
#include <cuda_runtime.h>
#include <math.h>

typedef unsigned long long ull;
#define ABS2 0x7FFFFFFF7FFFFFFFULL

// ---------------- scratch (device globals; no allocations) ----------------
__device__ float g_P [8192*128];
__device__ float g_Q [8192*128];
__device__ float g_U0[8192*128];
__device__ float g_U1[4096*128];
__device__ float g_ue0[64*128];
__device__ ull   g_cand[32*4*64];  // per-quadrant top-64 candidates (packed key|idx)
__device__ float g_H  [32*64*128];
__device__ float g_H2 [16*64*128];
__device__ float g_peA[32*64];
__device__ float g_ueA[32*64];
__device__ float g_peB[16*64];
__device__ float g_ueB[16*64];
__device__ int   g_subA[32*64*2];
__device__ int   g_subB[16*64*4];

// ---------------- f32x2 packed helpers ----------------
__device__ __forceinline__ ull pk2(float x, float y) {
    ull r; asm("mov.b64 %0, {%1,%2};" : "=l"(r) : "f"(x), "f"(y)); return r;
}
__device__ __forceinline__ void upk2(ull v, float &lo, float &hi) {
    asm("mov.b64 {%0,%1}, %2;" : "=f"(lo), "=f"(hi) : "l"(v));
}
__device__ __forceinline__ ull add2(ull a, ull b) {
    ull r; asm("add.rn.f32x2 %0, %1, %2;" : "=l"(r) : "l"(a), "l"(b)); return r;
}
__device__ __forceinline__ void fma2(ull &d, ull a, ull b) {
    asm("fma.rn.f32x2 %0, %1, %2, %0;" : "+l"(d) : "l"(a), "l"(b));
}

// monotone float->u32 key (unsigned asc == float asc)
__device__ __forceinline__ unsigned fkey(float v) {
    unsigned b = __float_as_uint(v);
    return (b & 0x80000000u) ? ~b : (b | 0x80000000u);
}
__device__ __forceinline__ float unfkey(unsigned k) {
    unsigned b = (k & 0x80000000u) ? (k & 0x7FFFFFFFu) : ~k;
    return __uint_as_float(b);
}
__device__ __forceinline__ ull umin64(ull a, ull b) { return a < b ? a : b; }

// ---------------- SGEMM: C[M,128] = A[M,256] @ W[256,128] (f32x2) ----------
__global__ __launch_bounds__(256) void gemm_all(
    const float* __restrict__ pos, const float* __restrict__ neg,
    const float* __restrict__ Wp1, const float* __restrict__ Wu1)
{
    const float* A; const float* W; float* C; int M;
    int g = blockIdx.y;
    if      (g == 0) { A = pos; W = Wp1;            C = g_P;  M = 8192; }
    else if (g == 1) { A = pos; W = Wp1 + 256*128;  C = g_Q;  M = 8192; }
    else if (g == 2) { A = pos; W = Wu1;            C = g_U0; M = 8192; }
    else             { A = neg; W = Wu1 + 256*128;  C = g_U1; M = 4096; }

    int row0 = blockIdx.x * 128;
    if (row0 >= M) return;

    __shared__ float sA[16][128];
    __shared__ float sB[16][128];

    int tid = threadIdx.x;
    int tx = tid & 15, ty = tid >> 4;

    ull acc2[8][4];
    #pragma unroll
    for (int i = 0; i < 8; i++)
        #pragma unroll
        for (int j = 0; j < 4; j++) acc2[i][j] = 0ull;

    for (int k0 = 0; k0 < 256; k0 += 16) {
        #pragma unroll
        for (int i = 0; i < 2; i++) {
            int idx = tid * 2 + i;
            int r  = idx >> 2;
            int c4 = (idx & 3) * 4;
            float4 v = *(const float4*)(A + (size_t)(row0 + r) * 256 + k0 + c4);
            sA[c4+0][r] = v.x; sA[c4+1][r] = v.y; sA[c4+2][r] = v.z; sA[c4+3][r] = v.w;
        }
        #pragma unroll
        for (int i = 0; i < 2; i++) {
            int idx = tid * 2 + i;
            int r  = idx >> 5;
            int c4 = (idx & 31) * 4;
            *(float4*)&sB[r][c4] = *(const float4*)(W + (size_t)(k0 + r) * 128 + c4);
        }
        __syncthreads();
        #pragma unroll
        for (int k = 0; k < 16; k++) {
            float4 a0 = *(const float4*)&sA[k][ty*8];
            float4 a1 = *(const float4*)&sA[k][ty*8 + 4];
            float4 b0 = *(const float4*)&sB[k][tx*8];
            float4 b1 = *(const float4*)&sB[k][tx*8 + 4];
            ull bp[4];
            bp[0] = pk2(b0.x, b0.y); bp[1] = pk2(b0.z, b0.w);
            bp[2] = pk2(b1.x, b1.y); bp[3] = pk2(b1.z, b1.w);
            float av[8] = {a0.x, a0.y, a0.z, a0.w, a1.x, a1.y, a1.z, a1.w};
            #pragma unroll
            for (int i = 0; i < 8; i++) {
                ull ap = pk2(av[i], av[i]);
                #pragma unroll
                for (int j = 0; j < 4; j++) fma2(acc2[i][j], ap, bp[j]);
            }
        }
        __syncthreads();
    }
    #pragma unroll
    for (int i = 0; i < 8; i++) {
        int r = row0 + ty*8 + i;
        float c[8];
        #pragma unroll
        for (int j = 0; j < 4; j++) upk2(acc2[i][j], c[2*j], c[2*j+1]);
        *(float4*)(C + (size_t)r * 128 + tx*8    ) = make_float4(c[0],c[1],c[2],c[3]);
        *(float4*)(C + (size_t)r * 128 + tx*8 + 4) = make_float4(c[4],c[5],c[6],c[7]);
    }
}

// ---------------- unary energies (h-pair packed, exact relu trick) --------
__global__ __launch_bounds__(256) void ue_kernel(
    const float* __restrict__ bu1, const float* __restrict__ Wu2,
    const float* __restrict__ bu2)
{
    int b = blockIdx.x;
    int mbase = blockIdx.y * 32;
    __shared__ ull sU1p[64*65];
    __shared__ float redbuf[8];
    int tid = threadIdx.x;
    int hp = tid & 63, ms = tid >> 6;

    for (int i = tid; i < 64*64; i += 256) {
        int n = i >> 6, p = i & 63;
        float2 v = *(const float2*)(g_U1 + (size_t)b*64*128 + n*128 + 2*p);
        sU1p[p*65 + n] = pk2(v.x + bu1[2*p], v.y + bu1[2*p+1]);
    }
    float w0 = Wu2[2*hp], w1 = Wu2[2*hp+1];
    float b2 = bu2[0];
    __syncthreads();

    for (int it = 0; it < 8; it++) {
        int m = mbase + it*4 + ms;
        float2 u0 = *(const float2*)(g_U0 + ((size_t)b*128 + m)*128 + 2*hp);
        ull up = pk2(u0.x, u0.y);
        ull acc = 0ull;
        #pragma unroll 8
        for (int n = 0; n < 64; n++) {
            ull s = add2(up, sU1p[hp*65 + n]);
            acc = add2(acc, add2(s, s & ABS2));   // += 2*relu
        }
        float lo, hi; upk2(acc, lo, hi);
        float v = lo*w0 + hi*w1;
        #pragma unroll
        for (int off = 16; off; off >>= 1) v += __shfl_down_sync(0xffffffffu, v, off);
        if ((tid & 31) == 0) redbuf[tid >> 5] = v;
        __syncthreads();
        if (hp == 0) {
            float t = redbuf[2*ms] + redbuf[2*ms+1];
            g_ue0[b*128 + m] = t * (0.5f/64.f) + b2;
        }
        __syncthreads();
    }
}

// ---------------- histogram radix threshold on packed (key32<<32|idx) -----
template<int E>
__device__ void radix_thresh(const ull (&pk)[E], int K, int* hist, int NW,
                             unsigned &T, int &rem)
{
    __shared__ int wred[8];
    __shared__ int s_bin, s_prev, s_rem;
    __shared__ unsigned s_pref;
    int tid = threadIdx.x, NT = blockDim.x;
    int wid = tid >> 5, lane = tid & 31;
    if (tid == 0) { s_pref = 0u; s_rem = K; }
    __syncthreads();
    #pragma unroll
    for (int pass = 0; pass < 4; pass++) {
        int shift = 24 - 8*pass;
        for (int i = tid; i < NW*256; i += NT) hist[i] = 0;
        __syncthreads();
        unsigned pmask = pass ? (0xFFFFFFFFu << (shift + 8)) : 0u;
        unsigned pref = s_pref;
        #pragma unroll
        for (int e = 0; e < E; e++) {
            unsigned k = (unsigned)(pk[e] >> 32);
            if ((k & pmask) == pref)
                atomicAdd(&hist[wid*256 + ((k >> shift) & 255)], 1);
        }
        __syncthreads();
        int tot = 0, v = 0;
        if (tid < 256) {
            for (int w = 0; w < NW; w++) tot += hist[w*256 + tid];
            v = tot;
            #pragma unroll
            for (int d = 1; d < 32; d <<= 1) {
                int u = __shfl_up_sync(0xffffffffu, v, d);
                if (lane >= d) v += u;
            }
            if (lane == 31) wred[wid] = v;
        }
        __syncthreads();
        if (tid == 0) {
            int acc = 0;
            for (int w = 0; w < 8; w++) { int t = wred[w]; wred[w] = acc; acc += t; }
        }
        __syncthreads();
        if (tid < 256) {
            v += wred[wid];
            int rm = s_rem;
            if (v >= rm && (v - tot) < rm) { s_bin = tid; s_prev = v - tot; }
        }
        __syncthreads();
        if (tid == 0) { s_rem -= s_prev; s_pref = pref | ((unsigned)s_bin << shift); }
        __syncthreads();
    }
    T = s_pref;
    rem = s_rem;
}

template<int E>
__device__ void collect_packed(ull (&pk)[E], int K, unsigned T, int rem, ull* cand)
{
    __shared__ ull wmin[32];
    __shared__ ull s_minv;
    __shared__ int s_cnt;
    int tid = threadIdx.x, NT = blockDim.x, NW = NT >> 5;
    if (tid == 0) s_cnt = 0;
    __syncthreads();
    #pragma unroll
    for (int e = 0; e < E; e++) {
        if ((unsigned)(pk[e] >> 32) < T) {
            int p = atomicAdd(&s_cnt, 1);
            cand[p] = pk[e];
        }
    }
    __syncthreads();
    int base = K - rem;
    for (int r = 0; r < rem; r++) {
        ull m = ~0ull;
        #pragma unroll
        for (int e = 0; e < E; e++)
            if ((unsigned)(pk[e] >> 32) == T) m = umin64(m, pk[e]);
        #pragma unroll
        for (int o = 16; o; o >>= 1) m = umin64(m, __shfl_down_sync(0xffffffffu, m, o));
        if ((tid & 31) == 0) wmin[tid >> 5] = m;
        __syncthreads();
        if (tid == 0) {
            ull mm = ~0ull;
            for (int w = 0; w < NW; w++) mm = umin64(mm, wmin[w]);
            s_minv = mm;
            cand[base + r] = mm;
        }
        __syncthreads();
        ull mm = s_minv;
        #pragma unroll
        for (int e = 0; e < E; e++)
            if (pk[e] == mm) pk[e] = ~0ull;
    }
    __syncthreads();
}

// ---------------- level-0: pair scores + per-quadrant exact top-64 --------
__global__ __launch_bounds__(256) void score0_kernel(
    const float* __restrict__ bp1, const float* __restrict__ Wp2,
    const float* __restrict__ bp2)
{
    int bn = blockIdx.y;
    int quad = blockIdx.x;
    int m0off = quad * 32;
    extern __shared__ ull smu[];
    ull* sH0p = smu;                 // [hp][m0] 64 x 33
    ull* sH1p = sH0p + 64*33;        // [hp][m1] 64 x 129
    ull* sw2h = sH1p + 64*129;       // 64
    ull* cand = sw2h + 64;           // 64
    float* sb0 = (float*)(cand + 64);// 32
    float* sb1 = sb0 + 32;           // 128
    int* hist  = (int*)(sb1 + 128);  // 8*256

    const float* h0 = g_P + (size_t)(2*bn  )*128*128 + (size_t)m0off*128;
    const float* h1 = g_Q + (size_t)(2*bn+1)*128*128;
    int tid = threadIdx.x;

    for (int i = tid; i < 32*64; i += 256) {
        int m = i >> 6, hp = i & 63;
        float2 v = *(const float2*)(h0 + m*128 + 2*hp);
        sH0p[hp*33 + m] = pk2(v.x, v.y);
    }
    for (int i = tid; i < 128*64; i += 256) {
        int m = i >> 6, hp = i & 63;
        float2 v = *(const float2*)(h1 + m*128 + 2*hp);
        sH1p[hp*129 + m] = pk2(v.x + bp1[2*hp], v.y + bp1[2*hp+1]);
    }
    if (tid < 64) sw2h[tid] = pk2(0.5f*Wp2[2*tid], 0.5f*Wp2[2*tid+1]);
    float b2 = bp2[0];
    if (tid < 32)  sb0[tid] = g_ue0[(2*bn)*128 + m0off + tid] - b2;
    if (tid < 128) sb1[tid] = g_ue0[(2*bn+1)*128 + tid];
    __syncthreads();

    int i0 = tid >> 5;
    int jl = tid & 31;
    ull acc[4][4];
    #pragma unroll
    for (int i = 0; i < 4; i++)
        #pragma unroll
        for (int j = 0; j < 4; j++) acc[i][j] = 0ull;

    for (int hp = 0; hp < 64; hp++) {
        ull wp = sw2h[hp];
        ull A[4], B[4];
        #pragma unroll
        for (int c = 0; c < 4; c++) A[c] = sH0p[hp*33 + i0 + 8*c];
        #pragma unroll
        for (int c = 0; c < 4; c++) B[c] = sH1p[hp*129 + jl + 32*c];
        #pragma unroll
        for (int i = 0; i < 4; i++)
            #pragma unroll
            for (int j = 0; j < 4; j++) {
                ull s = add2(A[i], B[j]);
                s = add2(s, s & ABS2);
                fma2(acc[i][j], s, wp);
            }
    }

    ull pk[16];
    #pragma unroll
    for (int i = 0; i < 4; i++)
        #pragma unroll
        for (int j = 0; j < 4; j++) {
            float lo, hi; upk2(acc[i][j], lo, hi);
            float val = sb0[i0 + 8*i] + sb1[jl + 32*j] - (lo + hi);
            int gidx = (m0off + i0 + 8*i) * 128 + (jl + 32*j);
            pk[i*4+j] = ((ull)fkey(val) << 32) | (unsigned)gidx;
        }

    unsigned T; int rem;
    radix_thresh<16>(pk, 64, hist, 8, T, rem);
    collect_packed<16>(pk, 64, T, rem, cand);

    if (tid < 64) g_cand[(bn*4 + quad)*64 + tid] = cand[tid];
}

// ---------------- level-0 final merge: 256 candidates -> exact top-64 -----
__global__ __launch_bounds__(512) void final0_kernel()
{
    __shared__ ull scand[256];
    __shared__ int sortedj[64];
    __shared__ float sortedv[64];
    __shared__ int subnew[128];
    int tid = threadIdx.x, bn = blockIdx.x;

    if (tid < 256) scand[tid] = g_cand[bn*256 + tid];
    __syncthreads();
    if (tid < 256) {
        ull c = scand[tid];
        int rank = 0;
        #pragma unroll 16
        for (int i = 0; i < 256; i++) rank += (scand[i] < c) ? 1 : 0;
        if (rank < 64) {
            sortedj[rank] = (int)(c & 0xFFFFFFFFu);
            sortedv[rank] = unfkey((unsigned)(c >> 32));
        }
    }
    __syncthreads();

    if (tid < 64) {
        int j = sortedj[tid]; int m0 = j >> 7, m1 = j & 127;
        float uen = g_ue0[(2*bn)*128 + m0] + g_ue0[(2*bn+1)*128 + m1];
        g_ueA[bn*64 + tid] = uen;
        g_peA[bn*64 + tid] = sortedv[tid] - uen;
        subnew[tid*2] = m0; subnew[tid*2 + 1] = m1;
        g_subA[(bn*64 + tid)*2    ] = m0;
        g_subA[(bn*64 + tid)*2 + 1] = m1;
    }
    __syncthreads();

    // H gather: float4, fully unrolled -> 8 LDGs in flight per thread
    const float4* X = (const float4*)((bn & 1) ? g_Q : g_P);
    float4* HO = (float4*)g_H;
    #pragma unroll
    for (int it = 0; it < 4; it++) {
        int idx = tid + 512*it;          // 0..2047 = 64 rows x 32 float4
        int r = idx >> 5, q = idx & 31;
        int r0 = subnew[r*2], r1 = subnew[r*2 + 1];
        float4 a = X[((size_t)(bn*2    )*128 + r0)*32 + q];
        float4 b = X[((size_t)(bn*2 + 1)*128 + r1)*32 + q];
        float4 o;
        o.x = (a.x + b.x)*0.5f; o.y = (a.y + b.y)*0.5f;
        o.z = (a.z + b.z)*0.5f; o.w = (a.w + b.w)*0.5f;
        HO[((size_t)bn*64 + r)*32 + q] = o;
    }
}

// ---------------- fused score+select for levels 1 & 2 ---------------------
template<int LVL>
__global__ __launch_bounds__(512) void level_kernel(
    const float* __restrict__ bp1, const float* __restrict__ Wp2,
    const float* __restrict__ bp2, float* __restrict__ d_out,
    const int* __restrict__ pos_classes, const int* __restrict__ target)
{
    extern __shared__ ull smu[];
    ull* sH0p = smu;                    // 64 x 65
    ull* sH1p = sH0p + 64*65;           // 64 x 65
    ull* sw2h = sH1p + 64*65;           // 64
    ull* cand = sw2h + 64;              // 64
    float* sb0 = (float*)(cand + 64);   // 64
    float* sb1 = sb0 + 64;              // 64
    int* hist  = (int*)(sb1 + 64);      // 16*256

    __shared__ int sortedj[64];
    __shared__ float sortedv[64];
    __shared__ int subnew[512];
    __shared__ ull awmin[16];
    __shared__ ull s_win;

    const float* ue_in = (LVL == 1) ? g_ueA : g_ueB;
    const float* pe_in = (LVL == 1) ? g_peA : g_peB;
    const int*  sub_in = (LVL == 1) ? g_subA : g_subB;
    const float* Hin   = (LVL == 1) ? g_H : g_H2;

    int tid = threadIdx.x, bn = blockIdx.x;

    if (LVL == 2) {
        // fused is_target: 8 blocks x 512 threads x 2 elements = 8192
        int i = bn*512 + tid;
        d_out[64 + i]        = (pos_classes[i]        == target[i >> 10])        ? 1.f : 0.f;
        d_out[64 + i + 4096] = (pos_classes[i + 4096] == target[(i + 4096) >> 10]) ? 1.f : 0.f;
    }

    const float* h0 = Hin + (size_t)(2*bn    )*64*128;
    const float* h1 = Hin + (size_t)(2*bn + 1)*64*128;

    for (int i = tid; i < 4096; i += 512) {
        int m = i >> 6, hp = i & 63;
        float2 v0 = *(const float2*)(h0 + m*128 + 2*hp);
        float2 v1 = *(const float2*)(h1 + m*128 + 2*hp);
        sH0p[hp*65 + m] = pk2(v0.x, v0.y);
        sH1p[hp*65 + m] = pk2(v1.x + bp1[2*hp], v1.y + bp1[2*hp+1]);
    }
    if (tid < 64) sw2h[tid] = pk2(0.5f*Wp2[2*tid], 0.5f*Wp2[2*tid+1]);
    float b2 = bp2[0];
    if (tid < 64) sb0[tid] = ue_in[(2*bn)*64 + tid] + pe_in[(2*bn)*64 + tid] - b2;
    else if (tid < 128) {
        int m = tid - 64;
        sb1[m] = ue_in[(2*bn+1)*64 + m] + pe_in[(2*bn+1)*64 + m];
    }
    __syncthreads();

    int m1 = tid & 63;
    int m0b = tid >> 6;
    ull acc[8];
    #pragma unroll
    for (int e = 0; e < 8; e++) acc[e] = 0ull;
    for (int hp = 0; hp < 64; hp++) {
        ull bb = sH1p[hp*65 + m1];
        ull wp = sw2h[hp];
        #pragma unroll
        for (int e = 0; e < 8; e++) {
            ull a = sH0p[hp*65 + m0b + 8*e];
            ull s = add2(a, bb);
            s = add2(s, s & ABS2);
            fma2(acc[e], s, wp);
        }
    }
    ull pk[8];
    #pragma unroll
    for (int e = 0; e < 8; e++) {
        float lo_, hi_; upk2(acc[e], lo_, hi_);
        float val = sb0[m0b + 8*e] + sb1[m1] - (lo_ + hi_);
        pk[e] = ((ull)fkey(val) << 32) | (unsigned)(tid + 512*e);
    }

    if (LVL == 2) {
        ull m = ~0ull;
        #pragma unroll
        for (int e = 0; e < 8; e++) m = umin64(m, pk[e]);
        #pragma unroll
        for (int o = 16; o; o >>= 1) m = umin64(m, __shfl_down_sync(0xffffffffu, m, o));
        if ((tid & 31) == 0) awmin[tid >> 5] = m;
        __syncthreads();
        if (tid == 0) {
            ull mm = ~0ull;
            for (int w = 0; w < 16; w++) mm = umin64(mm, awmin[w]);
            s_win = mm;
        }
        __syncthreads();
        if (tid < 8) {
            int j = (int)(s_win & 0xFFFFFFFFu);
            int m0 = j >> 6, m1s = j & 63;
            int v = (tid < 4) ? sub_in[((2*bn)*64 + m0)*4 + tid]
                              : sub_in[((2*bn+1)*64 + m1s)*4 + (tid - 4)];
            d_out[bn*8 + tid] = (float)v;
        }
        return;
    }

    // LVL == 1: exact top-64
    unsigned T; int rem;
    radix_thresh<8>(pk, 64, hist, 16, T, rem);
    collect_packed<8>(pk, 64, T, rem, cand);

    if (tid < 64) {
        ull c = cand[tid];
        int rank = 0;
        for (int i = 0; i < 64; i++) rank += (cand[i] < c) ? 1 : 0;
        sortedj[rank] = (int)(c & 0xFFFFFFFFu);
        sortedv[rank] = unfkey((unsigned)(c >> 32));
    }
    __syncthreads();

    if (tid < 64) {
        int j = sortedj[tid]; int m0 = j >> 6, m1s = j & 63;
        float uen = ue_in[(2*bn)*64 + m0] + ue_in[(2*bn+1)*64 + m1s];
        g_ueB[bn*64 + tid] = uen;
        g_peB[bn*64 + tid] = sortedv[tid] - uen;
        #pragma unroll
        for (int s = 0; s < 2; s++) {
            subnew[tid*4 + s]     = sub_in[((2*bn)*64 + m0)*2 + s];
            subnew[tid*4 + 2 + s] = sub_in[((2*bn+1)*64 + m1s)*2 + s];
        }
        #pragma unroll
        for (int s = 0; s < 4; s++)
            g_subB[(bn*64 + tid)*4 + s] = subnew[tid*4 + s];
    }
    __syncthreads();

    // H2 gather: float4, fully unrolled -> 16 LDGs in flight per thread
    const float4* X = (const float4*)((bn & 1) ? g_Q : g_P);
    float4* HO = (float4*)g_H2;
    #pragma unroll
    for (int it = 0; it < 4; it++) {
        int idx = tid + 512*it;          // 64 rows x 32 float4
        int r = idx >> 5, q = idx & 31;
        float4 s = make_float4(0.f, 0.f, 0.f, 0.f);
        #pragma unroll
        for (int s2i = 0; s2i < 4; s2i++) {
            float4 v = X[((size_t)(bn*4 + s2i)*128 + subnew[r*4 + s2i])*32 + q];
            s.x += v.x; s.y += v.y; s.z += v.z; s.w += v.w;
        }
        s.x *= 0.25f; s.y *= 0.25f; s.z *= 0.25f; s.w *= 0.25f;
        HO[((size_t)bn*64 + r)*32 + q] = s;
    }
}

// ---------------- launch ----------------
extern "C" void kernel_launch(void* const* d_in, const int* in_sizes, int n_in,
                              void* d_out, int out_size)
{
    const float* pos  = (const float*)d_in[0];
    const float* neg  = (const float*)d_in[1];
    const int*   pcls = (const int*)  d_in[2];
    const int*   tcls = (const int*)  d_in[3];
    const float* Wp1  = (const float*)d_in[4];
    const float* bp1  = (const float*)d_in[5];
    const float* Wp2  = (const float*)d_in[6];
    const float* bp2  = (const float*)d_in[7];
    const float* Wu1  = (const float*)d_in[8];
    const float* bu1  = (const float*)d_in[9];
    const float* Wu2  = (const float*)d_in[10];
    const float* bu2  = (const float*)d_in[11];
    float* out = (float*)d_out;

    size_t smS0 = (size_t)10496*8 + 160*4 + 2048*4;
    size_t smL  = (size_t)8448*8  + 128*4 + 4096*4;

    cudaFuncSetAttribute(score0_kernel,   cudaFuncAttributeMaxDynamicSharedMemorySize, (int)smS0);
    cudaFuncSetAttribute(level_kernel<1>, cudaFuncAttributeMaxDynamicSharedMemorySize, (int)smL);
    cudaFuncSetAttribute(level_kernel<2>, cudaFuncAttributeMaxDynamicSharedMemorySize, (int)smL);

    gemm_all<<<dim3(64, 4), 256>>>(pos, neg, Wp1, Wu1);
    ue_kernel<<<dim3(64, 4), 256>>>(bu1, Wu2, bu2);
    score0_kernel<<<dim3(4, 32), 256, smS0>>>(bp1, Wp2, bp2);
    final0_kernel<<<32, 512>>>();
    level_kernel<1><<<16, 512, smL>>>(bp1, Wp2, bp2, out, pcls, tcls);
    level_kernel<2><<<8, 512, smL>>>(bp1, Wp2, bp2, out, pcls, tcls);
}

// round 6
// speedup vs baseline: 1.9099x; 1.0162x over previous
#include <cuda_runtime.h>

typedef unsigned long long ull;
#define ABS2 0x7FFFFFFF7FFFFFFFULL

// ---------------- scratch (device globals; no allocations) ----------------
__device__ float g_P [8192*128];
__device__ float g_Q [8192*128];
__device__ float g_U0[8192*128];
__device__ float g_U1[4096*128];
__device__ float g_ue0[64*128];
__device__ ull   g_cand[32*4*64];
__device__ float g_H  [32*64*128];
__device__ float g_H2 [16*64*128];
__device__ float g_peA[32*64];
__device__ float g_ueA[32*64];
__device__ float g_peB[16*64];
__device__ float g_ueB[16*64];
__device__ int   g_subA[32*64*2];
__device__ int   g_subB[16*64*4];
__device__ ull   g_part[32];
__device__ unsigned g_sync[16];

// ---------------- f32x2 packed helpers ----------------
__device__ __forceinline__ ull pk2(float x, float y) {
    ull r; asm("mov.b64 %0, {%1,%2};" : "=l"(r) : "f"(x), "f"(y)); return r;
}
__device__ __forceinline__ void upk2(ull v, float &lo, float &hi) {
    asm("mov.b64 {%0,%1}, %2;" : "=f"(lo), "=f"(hi) : "l"(v));
}
__device__ __forceinline__ ull add2(ull a, ull b) {
    ull r; asm("add.rn.f32x2 %0, %1, %2;" : "=l"(r) : "l"(a), "l"(b)); return r;
}
__device__ __forceinline__ void fma2(ull &d, ull a, ull b) {
    asm("fma.rn.f32x2 %0, %1, %2, %0;" : "+l"(d) : "l"(a), "l"(b));
}
__device__ __forceinline__ unsigned fkey(float v) {
    unsigned b = __float_as_uint(v);
    return (b & 0x80000000u) ? ~b : (b | 0x80000000u);
}
__device__ __forceinline__ float unfkey(unsigned k) {
    unsigned b = (k & 0x80000000u) ? (k & 0x7FFFFFFFu) : ~k;
    return __uint_as_float(b);
}
__device__ __forceinline__ ull umin64(ull a, ull b) { return a < b ? a : b; }

// ---------------- spin grid barrier (all 128 blocks co-resident) ----------
#define NBLK 128
__device__ __forceinline__ void megabar(int phase) {
    __syncthreads();
    if (threadIdx.x == 0) {
        unsigned* p = &g_sync[phase];
        asm volatile("red.release.gpu.add.u32 [%0], 1;" :: "l"(p) : "memory");
        unsigned v;
        do {
            asm volatile("ld.acquire.gpu.u32 %0, [%1];" : "=r"(v) : "l"(p) : "memory");
        } while (v < NBLK);
    }
    __syncthreads();
}

// ---------------- SGEMM: C[M,128] = A[M,256] @ W[256,128] (f32x2) ----------
__global__ __launch_bounds__(256) void gemm_all(
    const float* __restrict__ pos, const float* __restrict__ neg,
    const float* __restrict__ Wp1, const float* __restrict__ Wu1)
{
    // zero the mega-kernel's grid-barrier counters (runs before mega launches)
    if (blockIdx.x == 0 && blockIdx.y == 0 && threadIdx.x < 16)
        g_sync[threadIdx.x] = 0u;

    const float* A; const float* W; float* C; int M;
    int g = blockIdx.y;
    if      (g == 0) { A = pos; W = Wp1;            C = g_P;  M = 8192; }
    else if (g == 1) { A = pos; W = Wp1 + 256*128;  C = g_Q;  M = 8192; }
    else if (g == 2) { A = pos; W = Wu1;            C = g_U0; M = 8192; }
    else             { A = neg; W = Wu1 + 256*128;  C = g_U1; M = 4096; }

    int row0 = blockIdx.x * 128;
    if (row0 >= M) return;

    __shared__ float sA[16][128];
    __shared__ float sB[16][128];

    int tid = threadIdx.x;
    int tx = tid & 15, ty = tid >> 4;

    ull acc2[8][4];
    #pragma unroll
    for (int i = 0; i < 8; i++)
        #pragma unroll
        for (int j = 0; j < 4; j++) acc2[i][j] = 0ull;

    for (int k0 = 0; k0 < 256; k0 += 16) {
        #pragma unroll
        for (int i = 0; i < 2; i++) {
            int idx = tid * 2 + i;
            int r  = idx >> 2;
            int c4 = (idx & 3) * 4;
            float4 v = *(const float4*)(A + (size_t)(row0 + r) * 256 + k0 + c4);
            sA[c4+0][r] = v.x; sA[c4+1][r] = v.y; sA[c4+2][r] = v.z; sA[c4+3][r] = v.w;
        }
        #pragma unroll
        for (int i = 0; i < 2; i++) {
            int idx = tid * 2 + i;
            int r  = idx >> 5;
            int c4 = (idx & 31) * 4;
            *(float4*)&sB[r][c4] = *(const float4*)(W + (size_t)(k0 + r) * 128 + c4);
        }
        __syncthreads();
        #pragma unroll
        for (int k = 0; k < 16; k++) {
            float4 a0 = *(const float4*)&sA[k][ty*8];
            float4 a1 = *(const float4*)&sA[k][ty*8 + 4];
            float4 b0 = *(const float4*)&sB[k][tx*8];
            float4 b1 = *(const float4*)&sB[k][tx*8 + 4];
            ull bp[4];
            bp[0] = pk2(b0.x, b0.y); bp[1] = pk2(b0.z, b0.w);
            bp[2] = pk2(b1.x, b1.y); bp[3] = pk2(b1.z, b1.w);
            float av[8] = {a0.x, a0.y, a0.z, a0.w, a1.x, a1.y, a1.z, a1.w};
            #pragma unroll
            for (int i = 0; i < 8; i++) {
                ull ap = pk2(av[i], av[i]);
                #pragma unroll
                for (int j = 0; j < 4; j++) fma2(acc2[i][j], ap, bp[j]);
            }
        }
        __syncthreads();
    }
    #pragma unroll
    for (int i = 0; i < 8; i++) {
        int r = row0 + ty*8 + i;
        float c[8];
        #pragma unroll
        for (int j = 0; j < 4; j++) upk2(acc2[i][j], c[2*j], c[2*j+1]);
        *(float4*)(C + (size_t)r * 128 + tx*8    ) = make_float4(c[0],c[1],c[2],c[3]);
        *(float4*)(C + (size_t)r * 128 + tx*8 + 4) = make_float4(c[4],c[5],c[6],c[7]);
    }
}

// ---------------- histogram radix threshold on packed (key32<<32|idx) -----
template<int E>
__device__ void radix_thresh(const ull (&pk)[E], int K, int* hist,
                             unsigned &T, int &rem)
{
    __shared__ int wred[8];
    __shared__ int s_bin, s_prev, s_rem;
    __shared__ unsigned s_pref;
    int tid = threadIdx.x;
    int wid = tid >> 5, lane = tid & 31;
    if (tid == 0) { s_pref = 0u; s_rem = K; }
    __syncthreads();
    #pragma unroll
    for (int pass = 0; pass < 4; pass++) {
        int shift = 24 - 8*pass;
        for (int i = tid; i < 8*256; i += 256) hist[i] = 0;
        __syncthreads();
        unsigned pmask = pass ? (0xFFFFFFFFu << (shift + 8)) : 0u;
        unsigned pref = s_pref;
        #pragma unroll
        for (int e = 0; e < E; e++) {
            unsigned k = (unsigned)(pk[e] >> 32);
            if ((k & pmask) == pref)
                atomicAdd(&hist[wid*256 + ((k >> shift) & 255)], 1);
        }
        __syncthreads();
        int tot = 0, v = 0;
        if (tid < 256) {
            for (int w = 0; w < 8; w++) tot += hist[w*256 + tid];
            v = tot;
            #pragma unroll
            for (int d = 1; d < 32; d <<= 1) {
                int u = __shfl_up_sync(0xffffffffu, v, d);
                if (lane >= d) v += u;
            }
            if (lane == 31) wred[wid] = v;
        }
        __syncthreads();
        if (tid == 0) {
            int acc = 0;
            for (int w = 0; w < 8; w++) { int t = wred[w]; wred[w] = acc; acc += t; }
        }
        __syncthreads();
        if (tid < 256) {
            v += wred[wid];
            int rm = s_rem;
            if (v >= rm && (v - tot) < rm) { s_bin = tid; s_prev = v - tot; }
        }
        __syncthreads();
        if (tid == 0) { s_rem -= s_prev; s_pref = pref | ((unsigned)s_bin << shift); }
        __syncthreads();
    }
    T = s_pref;
    rem = s_rem;
}

template<int E>
__device__ void collect_packed(ull (&pk)[E], int K, unsigned T, int rem, ull* cand)
{
    __shared__ ull wmin[8];
    __shared__ ull s_minv;
    __shared__ int s_cnt;
    int tid = threadIdx.x;
    if (tid == 0) s_cnt = 0;
    __syncthreads();
    #pragma unroll
    for (int e = 0; e < E; e++) {
        if ((unsigned)(pk[e] >> 32) < T) {
            int p = atomicAdd(&s_cnt, 1);
            cand[p] = pk[e];
        }
    }
    __syncthreads();
    int base = K - rem;
    for (int r = 0; r < rem; r++) {
        ull m = ~0ull;
        #pragma unroll
        for (int e = 0; e < E; e++)
            if ((unsigned)(pk[e] >> 32) == T) m = umin64(m, pk[e]);
        #pragma unroll
        for (int o = 16; o; o >>= 1) m = umin64(m, __shfl_down_sync(0xffffffffu, m, o));
        if ((tid & 31) == 0) wmin[tid >> 5] = m;
        __syncthreads();
        if (tid == 0) {
            ull mm = ~0ull;
            for (int w = 0; w < 8; w++) mm = umin64(mm, wmin[w]);
            s_minv = mm;
            cand[base + r] = mm;
        }
        __syncthreads();
        ull mm = s_minv;
        #pragma unroll
        for (int e = 0; e < E; e++)
            if (pk[e] == mm) pk[e] = ~0ull;
    }
    __syncthreads();
}

// 256-candidate merge: rank-sort by packed (key,idx); writes meta arrays.
__device__ __forceinline__ void merge256(
    char* smraw, int bn, int M_prev,
    const float* ue_src, float* ue_dst, float* pe_dst)
{
    ull*   scand   = (ull*)smraw;
    int*   sortedj = (int*)(scand + 256);
    float* sortedv = (float*)(sortedj + 64);
    int tid = threadIdx.x;
    scand[tid] = g_cand[bn*256 + tid];
    __syncthreads();
    ull c = scand[tid];
    int rank = 0;
    #pragma unroll 16
    for (int i = 0; i < 256; i++) rank += (scand[i] < c) ? 1 : 0;
    if (rank < 64) {
        sortedj[rank] = (int)(c & 0xFFFFFFFFu);
        sortedv[rank] = unfkey((unsigned)(c >> 32));
    }
    __syncthreads();
    if (tid < 64) {
        int j = sortedj[tid];
        int m0 = j / M_prev, m1 = j % M_prev;
        float uen = ue_src[(2*bn)*M_prev + m0] + ue_src[(2*bn+1)*M_prev + m1];
        ue_dst[bn*64 + tid] = uen;
        pe_dst[bn*64 + tid] = sortedv[tid] - uen;
        if (M_prev == 128) {   // level 0 -> subA
            g_subA[(bn*64 + tid)*2    ] = m0;
            g_subA[(bn*64 + tid)*2 + 1] = m1;
        } else {               // level 1 -> subB from subA
            g_subB[(bn*64 + tid)*4 + 0] = g_subA[((2*bn)*64 + m0)*2 + 0];
            g_subB[(bn*64 + tid)*4 + 1] = g_subA[((2*bn)*64 + m0)*2 + 1];
            g_subB[(bn*64 + tid)*4 + 2] = g_subA[((2*bn+1)*64 + m1)*2 + 0];
            g_subB[(bn*64 + tid)*4 + 3] = g_subA[((2*bn+1)*64 + m1)*2 + 1];
        }
    }
}

// ---------------- the persistent tail kernel ------------------------------
__global__ __launch_bounds__(256) void mega_kernel(
    const float* __restrict__ bp1, const float* __restrict__ Wp2,
    const float* __restrict__ bp2, const float* __restrict__ bu1,
    const float* __restrict__ Wu2, const float* __restrict__ bu2,
    const int* __restrict__ pcls, const int* __restrict__ tcls,
    float* __restrict__ d_out)
{
    extern __shared__ char smraw[];
    int tid = threadIdx.x, bid = blockIdx.x;

    // ===== Phase A: is_target + unary energies =====
    if (bid < 32) {
        int i = bid*256 + tid;
        d_out[64 + i] = (pcls[i] == tcls[i >> 10]) ? 1.f : 0.f;
    }
    {
        ull* sU1p = (ull*)smraw;        // 64 x 65
        __shared__ float redbuf[8];
        int b = bid >> 1;
        int mbase = (bid & 1) * 64;
        int hp = tid & 63, ms = tid >> 6;
        for (int i = tid; i < 64*64; i += 256) {
            int n = i >> 6, p = i & 63;
            float2 v = *(const float2*)(g_U1 + (size_t)b*64*128 + n*128 + 2*p);
            sU1p[p*65 + n] = pk2(v.x + bu1[2*p], v.y + bu1[2*p+1]);
        }
        float w0 = Wu2[2*hp], w1 = Wu2[2*hp+1];
        float b2u = bu2[0];
        __syncthreads();
        for (int it = 0; it < 16; it++) {
            int m = mbase + it*4 + ms;
            float2 u0 = *(const float2*)(g_U0 + ((size_t)b*128 + m)*128 + 2*hp);
            ull up = pk2(u0.x, u0.y);
            ull acc = 0ull;
            #pragma unroll 8
            for (int n = 0; n < 64; n++) {
                ull s = add2(up, sU1p[hp*65 + n]);
                acc = add2(acc, add2(s, s & ABS2));
            }
            float lo, hi; upk2(acc, lo, hi);
            float v = lo*w0 + hi*w1;
            #pragma unroll
            for (int off = 16; off; off >>= 1) v += __shfl_down_sync(0xffffffffu, v, off);
            if ((tid & 31) == 0) redbuf[tid >> 5] = v;
            __syncthreads();
            if (hp == 0) g_ue0[b*128 + m] = (redbuf[2*ms] + redbuf[2*ms+1]) * (0.5f/64.f) + b2u;
            __syncthreads();
        }
    }
    megabar(0);

    // ===== Phase B: level-0 pair scores + per-quadrant top-64 =====
    {
        int bn = bid >> 2, quad = bid & 3, m0off = quad * 32;
        ull* sH0p = (ull*)smraw;         // 64 x 33
        ull* sH1p = sH0p + 64*33;        // 64 x 129
        ull* sw2h = sH1p + 64*129;       // 64
        ull* cand = sw2h + 64;           // 64
        float* sb0 = (float*)(cand + 64);// 32
        float* sb1 = sb0 + 32;           // 128
        int* hist  = (int*)(sb1 + 128);  // 8*256

        const float* h0 = g_P + (size_t)(2*bn  )*128*128 + (size_t)m0off*128;
        const float* h1 = g_Q + (size_t)(2*bn+1)*128*128;

        for (int i = tid; i < 32*64; i += 256) {
            int m = i >> 6, hp = i & 63;
            float2 v = *(const float2*)(h0 + m*128 + 2*hp);
            sH0p[hp*33 + m] = pk2(v.x, v.y);
        }
        for (int i = tid; i < 128*64; i += 256) {
            int m = i >> 6, hp = i & 63;
            float2 v = *(const float2*)(h1 + m*128 + 2*hp);
            sH1p[hp*129 + m] = pk2(v.x + bp1[2*hp], v.y + bp1[2*hp+1]);
        }
        if (tid < 64) sw2h[tid] = pk2(0.5f*Wp2[2*tid], 0.5f*Wp2[2*tid+1]);
        float b2 = bp2[0];
        if (tid < 32)  sb0[tid] = g_ue0[(2*bn)*128 + m0off + tid] - b2;
        if (tid < 128) sb1[tid] = g_ue0[(2*bn+1)*128 + tid];
        __syncthreads();

        int i0 = tid >> 5, jl = tid & 31;
        ull acc[4][4];
        #pragma unroll
        for (int i = 0; i < 4; i++)
            #pragma unroll
            for (int j = 0; j < 4; j++) acc[i][j] = 0ull;
        for (int hp = 0; hp < 64; hp++) {
            ull wp = sw2h[hp];
            ull A[4], B[4];
            #pragma unroll
            for (int c = 0; c < 4; c++) A[c] = sH0p[hp*33 + i0 + 8*c];
            #pragma unroll
            for (int c = 0; c < 4; c++) B[c] = sH1p[hp*129 + jl + 32*c];
            #pragma unroll
            for (int i = 0; i < 4; i++)
                #pragma unroll
                for (int j = 0; j < 4; j++) {
                    ull s = add2(A[i], B[j]);
                    s = add2(s, s & ABS2);
                    fma2(acc[i][j], s, wp);
                }
        }
        ull pk[16];
        #pragma unroll
        for (int i = 0; i < 4; i++)
            #pragma unroll
            for (int j = 0; j < 4; j++) {
                float lo, hi; upk2(acc[i][j], lo, hi);
                float val = sb0[i0 + 8*i] + sb1[jl + 32*j] - (lo + hi);
                int gidx = (m0off + i0 + 8*i) * 128 + (jl + 32*j);
                pk[i*4+j] = ((ull)fkey(val) << 32) | (unsigned)gidx;
            }
        unsigned T; int rem;
        radix_thresh<16>(pk, 64, hist, T, rem);
        collect_packed<16>(pk, 64, T, rem, cand);
        if (tid < 64) g_cand[(bn*4 + quad)*64 + tid] = cand[tid];
    }
    megabar(1);

    // ===== Phase C: level-0 merge (32 blocks) =====
    if (bid < 32)
        merge256(smraw, bid, 128, g_ue0, g_ueA, g_peA);
    megabar(2);

    // ===== Phase D: H gather, spread over all 128 blocks =====
    {
        int bn = bid >> 2, rq = (bid & 3) * 16;
        const float4* X = (const float4*)((bn & 1) ? g_Q : g_P);
        float4* HO = (float4*)g_H;
        #pragma unroll
        for (int it = 0; it < 2; it++) {
            int idx = tid + 256*it;            // 512 = 16 rows x 32 q
            int r = rq + (idx >> 5), q = idx & 31;
            int r0 = g_subA[(bn*64 + r)*2], r1 = g_subA[(bn*64 + r)*2 + 1];
            float4 a = X[((size_t)(bn*2    )*128 + r0)*32 + q];
            float4 b = X[((size_t)(bn*2 + 1)*128 + r1)*32 + q];
            HO[((size_t)bn*64 + r)*32 + q] =
                make_float4((a.x+b.x)*0.5f, (a.y+b.y)*0.5f, (a.z+b.z)*0.5f, (a.w+b.w)*0.5f);
        }
    }
    megabar(3);

    // ===== Phase E: level-1 strip scores + strip top-64 (64 blocks) =====
    if (bid < 64) {
        int bn = bid >> 2, quad = bid & 3, m0off = quad * 16;
        ull* sH0p = (ull*)smraw;          // 64 x 17
        ull* sH1p = sH0p + 64*17;         // 64 x 65
        ull* sw2h = sH1p + 64*65;         // 64
        ull* cand = sw2h + 64;            // 64
        float* sb0 = (float*)(cand + 64); // 16
        float* sb1 = sb0 + 16;            // 64
        int* hist  = (int*)(sb1 + 64);    // 8*256

        const float* h0 = g_H + (size_t)(2*bn  )*64*128 + (size_t)m0off*128;
        const float* h1 = g_H + (size_t)(2*bn+1)*64*128;
        for (int i = tid; i < 16*64; i += 256) {
            int m = i >> 6, hp = i & 63;
            float2 v = *(const float2*)(h0 + m*128 + 2*hp);
            sH0p[hp*17 + m] = pk2(v.x, v.y);
        }
        for (int i = tid; i < 64*64; i += 256) {
            int m = i >> 6, hp = i & 63;
            float2 v = *(const float2*)(h1 + m*128 + 2*hp);
            sH1p[hp*65 + m] = pk2(v.x + bp1[2*hp], v.y + bp1[2*hp+1]);
        }
        if (tid < 64) sw2h[tid] = pk2(0.5f*Wp2[2*tid], 0.5f*Wp2[2*tid+1]);
        float b2 = bp2[0];
        if (tid < 16) sb0[tid] = g_ueA[(2*bn)*64 + m0off + tid]
                               + g_peA[(2*bn)*64 + m0off + tid] - b2;
        if (tid >= 32 && tid < 96) {
            int m = tid - 32;
            sb1[m] = g_ueA[(2*bn+1)*64 + m] + g_peA[(2*bn+1)*64 + m];
        }
        __syncthreads();

        int m1 = tid & 63, m0b = tid >> 6;
        ull acc[4] = {0ull, 0ull, 0ull, 0ull};
        for (int hp = 0; hp < 64; hp++) {
            ull bb = sH1p[hp*65 + m1];
            ull wp = sw2h[hp];
            #pragma unroll
            for (int e = 0; e < 4; e++) {
                ull a = sH0p[hp*17 + m0b*4 + e];
                ull s = add2(a, bb);
                s = add2(s, s & ABS2);
                fma2(acc[e], s, wp);
            }
        }
        ull pk[4];
        #pragma unroll
        for (int e = 0; e < 4; e++) {
            float lo, hi; upk2(acc[e], lo, hi);
            float val = sb0[m0b*4 + e] + sb1[m1] - (lo + hi);
            int gidx = (m0off + m0b*4 + e) * 64 + m1;
            pk[e] = ((ull)fkey(val) << 32) | (unsigned)gidx;
        }
        unsigned T; int rem;
        radix_thresh<4>(pk, 64, hist, T, rem);
        collect_packed<4>(pk, 64, T, rem, cand);
        if (tid < 64) g_cand[(bn*4 + quad)*64 + tid] = cand[tid];
    }
    megabar(4);

    // ===== Phase F: level-1 merge (16 blocks) =====
    if (bid < 16)
        merge256(smraw, bid, 64, g_ueA, g_ueB, g_peB);
    megabar(5);

    // ===== Phase G: H2 gather, spread over all 128 blocks =====
    {
        int bn = bid >> 3, re = (bid & 7) * 8;
        const float4* X = (const float4*)((bn & 1) ? g_Q : g_P);
        float4* HO = (float4*)g_H2;
        int r = re + (tid >> 5), q = tid & 31;
        const int* sb = &g_subB[(bn*64 + r)*4];
        float4 s = make_float4(0.f, 0.f, 0.f, 0.f);
        #pragma unroll
        for (int i = 0; i < 4; i++) {
            float4 v = X[((size_t)(bn*4 + i)*128 + sb[i])*32 + q];
            s.x += v.x; s.y += v.y; s.z += v.z; s.w += v.w;
        }
        HO[((size_t)bn*64 + r)*32 + q] =
            make_float4(s.x*0.25f, s.y*0.25f, s.z*0.25f, s.w*0.25f);
    }
    megabar(6);

    // ===== Phase H: level-2 strip argmin (32 blocks) =====
    if (bid < 32) {
        int bn = bid >> 2, quad = bid & 3, m0off = quad * 16;
        ull* sH0p = (ull*)smraw;
        ull* sH1p = sH0p + 64*17;
        ull* sw2h = sH1p + 64*65;
        float* sb0 = (float*)(sw2h + 64);
        float* sb1 = sb0 + 16;
        __shared__ ull hwmin[8];

        const float* h0 = g_H2 + (size_t)(2*bn  )*64*128 + (size_t)m0off*128;
        const float* h1 = g_H2 + (size_t)(2*bn+1)*64*128;
        for (int i = tid; i < 16*64; i += 256) {
            int m = i >> 6, hp = i & 63;
            float2 v = *(const float2*)(h0 + m*128 + 2*hp);
            sH0p[hp*17 + m] = pk2(v.x, v.y);
        }
        for (int i = tid; i < 64*64; i += 256) {
            int m = i >> 6, hp = i & 63;
            float2 v = *(const float2*)(h1 + m*128 + 2*hp);
            sH1p[hp*65 + m] = pk2(v.x + bp1[2*hp], v.y + bp1[2*hp+1]);
        }
        if (tid < 64) sw2h[tid] = pk2(0.5f*Wp2[2*tid], 0.5f*Wp2[2*tid+1]);
        float b2 = bp2[0];
        if (tid < 16) sb0[tid] = g_ueB[(2*bn)*64 + m0off + tid]
                               + g_peB[(2*bn)*64 + m0off + tid] - b2;
        if (tid >= 32 && tid < 96) {
            int m = tid - 32;
            sb1[m] = g_ueB[(2*bn+1)*64 + m] + g_peB[(2*bn+1)*64 + m];
        }
        __syncthreads();

        int m1 = tid & 63, m0b = tid >> 6;
        ull acc[4] = {0ull, 0ull, 0ull, 0ull};
        for (int hp = 0; hp < 64; hp++) {
            ull bb = sH1p[hp*65 + m1];
            ull wp = sw2h[hp];
            #pragma unroll
            for (int e = 0; e < 4; e++) {
                ull a = sH0p[hp*17 + m0b*4 + e];
                ull s = add2(a, bb);
                s = add2(s, s & ABS2);
                fma2(acc[e], s, wp);
            }
        }
        ull mbest = ~0ull;
        #pragma unroll
        for (int e = 0; e < 4; e++) {
            float lo, hi; upk2(acc[e], lo, hi);
            float val = sb0[m0b*4 + e] + sb1[m1] - (lo + hi);
            int gidx = (m0off + m0b*4 + e) * 64 + m1;
            mbest = umin64(mbest, ((ull)fkey(val) << 32) | (unsigned)gidx);
        }
        #pragma unroll
        for (int o = 16; o; o >>= 1) mbest = umin64(mbest, __shfl_down_sync(0xffffffffu, mbest, o));
        if ((tid & 31) == 0) hwmin[tid >> 5] = mbest;
        __syncthreads();
        if (tid == 0) {
            ull mm = ~0ull;
            #pragma unroll
            for (int w = 0; w < 8; w++) mm = umin64(mm, hwmin[w]);
            g_part[bid] = mm;
        }
    }
    megabar(7);

    // ===== Phase I: level-2 final (8 blocks, 1 thread each) =====
    if (bid < 8 && tid == 0) {
        ull m = umin64(umin64(g_part[bid*4], g_part[bid*4+1]),
                       umin64(g_part[bid*4+2], g_part[bid*4+3]));
        int j = (int)(m & 0xFFFFFFFFu);
        int m0 = j >> 6, m1 = j & 63;
        #pragma unroll
        for (int s = 0; s < 4; s++) {
            d_out[bid*8 + s]     = (float)g_subB[((2*bid)*64 + m0)*4 + s];
            d_out[bid*8 + 4 + s] = (float)g_subB[((2*bid+1)*64 + m1)*4 + s];
        }
    }
}

// ---------------- launch ----------------
extern "C" void kernel_launch(void* const* d_in, const int* in_sizes, int n_in,
                              void* d_out, int out_size)
{
    const float* pos  = (const float*)d_in[0];
    const float* neg  = (const float*)d_in[1];
    const int*   pcls = (const int*)  d_in[2];
    const int*   tcls = (const int*)  d_in[3];
    const float* Wp1  = (const float*)d_in[4];
    const float* bp1  = (const float*)d_in[5];
    const float* Wp2  = (const float*)d_in[6];
    const float* bp2  = (const float*)d_in[7];
    const float* Wu1  = (const float*)d_in[8];
    const float* bu1  = (const float*)d_in[9];
    const float* Wu2  = (const float*)d_in[10];
    const float* bu2  = (const float*)d_in[11];
    float* out = (float*)d_out;

    // max dynamic smem across phases = phase B: 10496 ull + 160 f + 2048 int
    size_t smM = (size_t)10496*8 + 160*4 + 2048*4;   // 92,800 B

    cudaFuncSetAttribute(mega_kernel, cudaFuncAttributeMaxDynamicSharedMemorySize, (int)smM);

    gemm_all<<<dim3(64, 4), 256>>>(pos, neg, Wp1, Wu1);
    mega_kernel<<<NBLK, 256, smM>>>(bp1, Wp2, bp2, bu1, Wu2, bu2, pcls, tcls, out);
}

// round 7
// speedup vs baseline: 2.1213x; 1.1107x over previous
#include <cuda_runtime.h>

typedef unsigned long long ull;
#define ABS2 0x7FFFFFFF7FFFFFFFULL
#define NBLK 128

// ---------------- scratch (device globals; no allocations) ----------------
__device__ float g_P [8192*128];
__device__ float g_Q [8192*128];
__device__ float g_U0[8192*128];
__device__ float g_U1[4096*128];
__device__ float g_ue0[64*128];
__device__ ull   g_cand[16*512];   // max: lvl1 = 16 bn x 8 strips x 64
__device__ float g_H  [32*64*128];
__device__ float g_H2 [16*64*128];
__device__ float g_peA[32*64];
__device__ float g_ueA[32*64];
__device__ float g_peB[16*64];
__device__ float g_ueB[16*64];
__device__ int   g_subA[32*64*2];
__device__ int   g_subB[16*64*4];
__device__ ull   g_part[8];
__device__ unsigned g_done[8];
__device__ unsigned g_sync[8];

// ---------------- helpers ----------------
__device__ __forceinline__ ull pk2(float x, float y) {
    ull r; asm("mov.b64 %0, {%1,%2};" : "=l"(r) : "f"(x), "f"(y)); return r;
}
__device__ __forceinline__ void upk2(ull v, float &lo, float &hi) {
    asm("mov.b64 {%0,%1}, %2;" : "=f"(lo), "=f"(hi) : "l"(v));
}
__device__ __forceinline__ ull add2(ull a, ull b) {
    ull r; asm("add.rn.f32x2 %0, %1, %2;" : "=l"(r) : "l"(a), "l"(b)); return r;
}
__device__ __forceinline__ void fma2(ull &d, ull a, ull b) {
    asm("fma.rn.f32x2 %0, %1, %2, %0;" : "+l"(d) : "l"(a), "l"(b));
}
__device__ __forceinline__ unsigned fkey(float v) {
    unsigned b = __float_as_uint(v);
    return (b & 0x80000000u) ? ~b : (b | 0x80000000u);
}
__device__ __forceinline__ float unfkey(unsigned k) {
    unsigned b = (k & 0x80000000u) ? (k & 0x7FFFFFFFu) : ~k;
    return __uint_as_float(b);
}
__device__ __forceinline__ ull umin64(ull a, ull b) { return a < b ? a : b; }

__device__ __forceinline__ void megabar(int phase) {
    __syncthreads();
    if (threadIdx.x == 0) {
        unsigned* p = &g_sync[phase];
        asm volatile("red.release.gpu.add.u32 [%0], 1;" :: "l"(p) : "memory");
        unsigned v;
        do {
            asm volatile("ld.acquire.gpu.u32 %0, [%1];" : "=r"(v) : "l"(p) : "memory");
        } while (v < NBLK);
    }
    __syncthreads();
}

// ---------------- SGEMM, double-buffered ----------------
__global__ __launch_bounds__(256) void gemm_all(
    const float* __restrict__ pos, const float* __restrict__ neg,
    const float* __restrict__ Wp1, const float* __restrict__ Wu1)
{
    if (blockIdx.x == 0 && blockIdx.y == 0) {
        if (threadIdx.x < 8)  g_sync[threadIdx.x] = 0u;
        if (threadIdx.x >= 8 && threadIdx.x < 16) {
            g_part[threadIdx.x - 8] = ~0ull;
            g_done[threadIdx.x - 8] = 0u;
        }
    }

    const float* A; const float* W; float* C; int M;
    int g = blockIdx.y;
    if      (g == 0) { A = pos; W = Wp1;            C = g_P;  M = 8192; }
    else if (g == 1) { A = pos; W = Wp1 + 256*128;  C = g_Q;  M = 8192; }
    else if (g == 2) { A = pos; W = Wu1;            C = g_U0; M = 8192; }
    else             { A = neg; W = Wu1 + 256*128;  C = g_U1; M = 4096; }

    int row0 = blockIdx.x * 128;
    if (row0 >= M) return;

    __shared__ float sA[2][16][128];
    __shared__ float sB[2][16][128];

    int tid = threadIdx.x;
    int tx = tid & 15, ty = tid >> 4;

    int aR[2], aC[2], bR[2], bC[2];
    #pragma unroll
    for (int i = 0; i < 2; i++) {
        int idx = tid * 2 + i;
        aR[i] = idx >> 2;  aC[i] = (idx & 3) * 4;
        bR[i] = idx >> 5;  bC[i] = (idx & 31) * 4;
    }

    float4 ra[2], rb[2];
    #pragma unroll
    for (int i = 0; i < 2; i++) {
        ra[i] = *(const float4*)(A + (size_t)(row0 + aR[i]) * 256 + aC[i]);
        rb[i] = *(const float4*)(W + (size_t)bR[i] * 128 + bC[i]);
    }

    ull acc2[8][4];
    #pragma unroll
    for (int i = 0; i < 8; i++)
        #pragma unroll
        for (int j = 0; j < 4; j++) acc2[i][j] = 0ull;

    for (int k0 = 0; k0 < 16; k0++) {
        int buf = k0 & 1;
        #pragma unroll
        for (int i = 0; i < 2; i++) {
            sA[buf][aC[i]+0][aR[i]] = ra[i].x;
            sA[buf][aC[i]+1][aR[i]] = ra[i].y;
            sA[buf][aC[i]+2][aR[i]] = ra[i].z;
            sA[buf][aC[i]+3][aR[i]] = ra[i].w;
            *(float4*)&sB[buf][bR[i]][bC[i]] = rb[i];
        }
        __syncthreads();
        if (k0 < 15) {
            #pragma unroll
            for (int i = 0; i < 2; i++) {
                ra[i] = *(const float4*)(A + (size_t)(row0 + aR[i]) * 256 + (k0+1)*16 + aC[i]);
                rb[i] = *(const float4*)(W + (size_t)((k0+1)*16 + bR[i]) * 128 + bC[i]);
            }
        }
        #pragma unroll
        for (int k = 0; k < 16; k++) {
            float4 a0 = *(const float4*)&sA[buf][k][ty*8];
            float4 a1 = *(const float4*)&sA[buf][k][ty*8 + 4];
            ull bp[4];
            bp[0] = *(const ull*)&sB[buf][k][tx*8];
            bp[1] = *(const ull*)&sB[buf][k][tx*8 + 2];
            bp[2] = *(const ull*)&sB[buf][k][tx*8 + 4];
            bp[3] = *(const ull*)&sB[buf][k][tx*8 + 6];
            float av[8] = {a0.x, a0.y, a0.z, a0.w, a1.x, a1.y, a1.z, a1.w};
            #pragma unroll
            for (int i = 0; i < 8; i++) {
                ull ap = pk2(av[i], av[i]);
                #pragma unroll
                for (int j = 0; j < 4; j++) fma2(acc2[i][j], ap, bp[j]);
            }
        }
    }
    #pragma unroll
    for (int i = 0; i < 8; i++) {
        int r = row0 + ty*8 + i;
        float c[8];
        #pragma unroll
        for (int j = 0; j < 4; j++) upk2(acc2[i][j], c[2*j], c[2*j+1]);
        *(float4*)(C + (size_t)r * 128 + tx*8    ) = make_float4(c[0],c[1],c[2],c[3]);
        *(float4*)(C + (size_t)r * 128 + tx*8 + 4) = make_float4(c[4],c[5],c[6],c[7]);
    }
}

// ---------------- radix threshold (512 threads, NW warps) -----------------
template<int E, int NW>
__device__ void radix_thresh(const ull (&pk)[E], int K, int* hist,
                             unsigned &T, int &rem)
{
    __shared__ int wred[8];
    __shared__ int s_bin, s_prev, s_rem;
    __shared__ unsigned s_pref;
    int tid = threadIdx.x;
    int wid = tid >> 5, lane = tid & 31;
    if (tid == 0) { s_pref = 0u; s_rem = K; }
    __syncthreads();
    #pragma unroll
    for (int pass = 0; pass < 4; pass++) {
        int shift = 24 - 8*pass;
        for (int i = tid; i < NW*256; i += blockDim.x) hist[i] = 0;
        __syncthreads();
        unsigned pmask = pass ? (0xFFFFFFFFu << (shift + 8)) : 0u;
        unsigned pref = s_pref;
        #pragma unroll
        for (int e = 0; e < E; e++) {
            unsigned k = (unsigned)(pk[e] >> 32);
            if ((k & pmask) == pref)
                atomicAdd(&hist[wid*256 + ((k >> shift) & 255)], 1);
        }
        __syncthreads();
        int tot = 0, v = 0;
        if (tid < 256) {
            #pragma unroll
            for (int w = 0; w < NW; w++) tot += hist[w*256 + tid];
            v = tot;
            #pragma unroll
            for (int d = 1; d < 32; d <<= 1) {
                int u = __shfl_up_sync(0xffffffffu, v, d);
                if (lane >= d) v += u;
            }
            if (lane == 31) wred[wid] = v;
        }
        __syncthreads();
        if (tid == 0) {
            int acc = 0;
            #pragma unroll
            for (int w = 0; w < 8; w++) { int t = wred[w]; wred[w] = acc; acc += t; }
        }
        __syncthreads();
        if (tid < 256) {
            v += wred[wid];
            int rm = s_rem;
            if (v >= rm && (v - tot) < rm) { s_bin = tid; s_prev = v - tot; }
        }
        __syncthreads();
        if (tid == 0) { s_rem -= s_prev; s_pref = pref | ((unsigned)s_bin << shift); }
        __syncthreads();
    }
    T = s_pref;
    rem = s_rem;
}

template<int E, int NW>
__device__ void collect_packed(ull (&pk)[E], int K, unsigned T, int rem, ull* cand)
{
    __shared__ ull wmin[NW];
    __shared__ ull s_minv;
    __shared__ int s_cnt;
    int tid = threadIdx.x;
    if (tid == 0) s_cnt = 0;
    __syncthreads();
    #pragma unroll
    for (int e = 0; e < E; e++) {
        if ((unsigned)(pk[e] >> 32) < T) {
            int p = atomicAdd(&s_cnt, 1);
            cand[p] = pk[e];
        }
    }
    __syncthreads();
    int base = K - rem;
    for (int r = 0; r < rem; r++) {
        ull m = ~0ull;
        #pragma unroll
        for (int e = 0; e < E; e++)
            if ((unsigned)(pk[e] >> 32) == T) m = umin64(m, pk[e]);
        #pragma unroll
        for (int o = 16; o; o >>= 1) m = umin64(m, __shfl_down_sync(0xffffffffu, m, o));
        if ((tid & 31) == 0) wmin[tid >> 5] = m;
        __syncthreads();
        if (tid == 0) {
            ull mm = ~0ull;
            #pragma unroll
            for (int w = 0; w < NW; w++) mm = umin64(mm, wmin[w]);
            s_minv = mm;
            cand[base + r] = mm;
        }
        __syncthreads();
        ull mm = s_minv;
        #pragma unroll
        for (int e = 0; e < E; e++)
            if (pk[e] == mm) pk[e] = ~0ull;
    }
    __syncthreads();
}

// ---------------- persistent tail kernel (512 threads) --------------------
__global__ __launch_bounds__(512) void mega_kernel(
    const float* __restrict__ bp1, const float* __restrict__ Wp2,
    const float* __restrict__ bp2, const float* __restrict__ bu1,
    const float* __restrict__ Wu2, const float* __restrict__ bu2,
    const int* __restrict__ pcls, const int* __restrict__ tcls,
    float* __restrict__ d_out)
{
    extern __shared__ char smraw[];
    ull* smu = (ull*)smraw;
    int tid = threadIdx.x, bid = blockIdx.x;

    // ===== Phase A: is_target + unary energies =====
    if (bid < 16) {
        int i = bid*512 + tid;
        d_out[64 + i] = (pcls[i] == tcls[i >> 10]) ? 1.f : 0.f;
    }
    {
        ull* sU1p = smu;                // 64 x 65
        __shared__ float redbuf[16];
        int b = bid >> 1;
        int mbase = (bid & 1) * 64;
        int hp = tid & 63, ms = tid >> 6;
        for (int i = tid; i < 64*64; i += 512) {
            int n = i >> 6, p = i & 63;
            float2 v = *(const float2*)(g_U1 + (size_t)b*64*128 + n*128 + 2*p);
            sU1p[p*65 + n] = pk2(v.x + bu1[2*p], v.y + bu1[2*p+1]);
        }
        float w0 = Wu2[2*hp], w1 = Wu2[2*hp+1];
        float b2u = bu2[0];
        __syncthreads();
        for (int it = 0; it < 8; it++) {
            int m = mbase + it*8 + ms;
            float2 u0 = *(const float2*)(g_U0 + ((size_t)b*128 + m)*128 + 2*hp);
            ull up = pk2(u0.x, u0.y);
            ull acc = 0ull;
            #pragma unroll 8
            for (int n = 0; n < 64; n++) {
                ull s = add2(up, sU1p[hp*65 + n]);
                acc = add2(acc, add2(s, s & ABS2));
            }
            float lo, hi; upk2(acc, lo, hi);
            float v = lo*w0 + hi*w1;
            #pragma unroll
            for (int off = 16; off; off >>= 1) v += __shfl_down_sync(0xffffffffu, v, off);
            if ((tid & 31) == 0) redbuf[tid >> 5] = v;
            __syncthreads();
            if (hp == 0) g_ue0[b*128 + m] = (redbuf[2*ms] + redbuf[2*ms+1]) * (0.5f/64.f) + b2u;
            __syncthreads();
        }
    }
    megabar(0);

    // ===== Phase B: level-0 quadrant scores + top-64 =====
    {
        int bn = bid >> 2, quad = bid & 3, m0off = quad * 32;
        ull* sH0p = smu;                 // 64 x 33
        ull* sH1p = sH0p + 64*33;        // 64 x 129
        ull* sw2h = sH1p + 64*129;       // 64
        ull* cand = sw2h + 64;           // 64
        float* sb0 = (float*)(cand + 64);// 32
        float* sb1 = sb0 + 32;           // 128
        int* hist  = (int*)(sb1 + 128);  // 16*256

        const float* h0 = g_P + (size_t)(2*bn  )*128*128 + (size_t)m0off*128;
        const float* h1 = g_Q + (size_t)(2*bn+1)*128*128;

        for (int i = tid; i < 32*64; i += 512) {
            int m = i >> 6, hp = i & 63;
            float2 v = *(const float2*)(h0 + m*128 + 2*hp);
            sH0p[hp*33 + m] = pk2(v.x, v.y);
        }
        for (int i = tid; i < 128*64; i += 512) {
            int m = i >> 6, hp = i & 63;
            float2 v = *(const float2*)(h1 + m*128 + 2*hp);
            sH1p[hp*129 + m] = pk2(v.x + bp1[2*hp], v.y + bp1[2*hp+1]);
        }
        if (tid < 64) sw2h[tid] = pk2(0.5f*Wp2[2*tid], 0.5f*Wp2[2*tid+1]);
        float b2 = bp2[0];
        if (tid >= 64 && tid < 96)   sb0[tid-64] = g_ue0[(2*bn)*128 + m0off + tid-64] - b2;
        if (tid >= 128 && tid < 256) sb1[tid-128] = g_ue0[(2*bn+1)*128 + tid-128];
        __syncthreads();

        int i0 = tid >> 6, jl = tid & 63;
        ull acc[4][2];
        #pragma unroll
        for (int c = 0; c < 4; c++) { acc[c][0] = 0ull; acc[c][1] = 0ull; }
        for (int hp = 0; hp < 64; hp++) {
            ull wp = sw2h[hp];
            ull A[4], B[2];
            #pragma unroll
            for (int c = 0; c < 4; c++) A[c] = sH0p[hp*33 + i0 + 8*c];
            B[0] = sH1p[hp*129 + jl];
            B[1] = sH1p[hp*129 + jl + 64];
            #pragma unroll
            for (int c = 0; c < 4; c++)
                #pragma unroll
                for (int j = 0; j < 2; j++) {
                    ull s = add2(A[c], B[j]);
                    s = add2(s, s & ABS2);
                    fma2(acc[c][j], s, wp);
                }
        }
        ull pk[8];
        #pragma unroll
        for (int c = 0; c < 4; c++)
            #pragma unroll
            for (int j = 0; j < 2; j++) {
                float lo, hi; upk2(acc[c][j], lo, hi);
                int m0 = i0 + 8*c, m1 = jl + 64*j;
                float val = sb0[m0] + sb1[m1] - (lo + hi);
                int gidx = (m0off + m0) * 128 + m1;
                pk[c*2+j] = ((ull)fkey(val) << 32) | (unsigned)gidx;
            }
        unsigned T; int rem;
        radix_thresh<8,16>(pk, 64, hist, T, rem);
        collect_packed<8,16>(pk, 64, T, rem, cand);
        if (tid < 64) g_cand[(bn*4 + quad)*64 + tid] = cand[tid];
    }
    megabar(1);

    // ===== Phase C+D: level-0 merge (x4 redundant) + H gather =====
    {
        int bn = bid >> 2;
        ull*   scand = smu;                // 256
        int*   s_m0  = (int*)(scand + 256);// 64
        int*   s_m1  = s_m0 + 64;          // 64
        float* s_v   = (float*)(s_m1 + 64);// 64
        if (tid < 256) scand[tid] = g_cand[bn*256 + tid];
        __syncthreads();
        if (tid < 256) {
            ull c = scand[tid]; int rank = 0;
            #pragma unroll 16
            for (int i = 0; i < 256; i++) rank += (scand[i] < c) ? 1 : 0;
            if (rank < 64) {
                int j = (int)(c & 0xFFFFFFFFu);
                s_m0[rank] = j >> 7; s_m1[rank] = j & 127;
                s_v[rank] = unfkey((unsigned)(c >> 32));
            }
        }
        __syncthreads();
        if (tid < 64) {
            int m0 = s_m0[tid], m1 = s_m1[tid];
            float uen = g_ue0[(2*bn)*128 + m0] + g_ue0[(2*bn+1)*128 + m1];
            g_ueA[bn*64 + tid] = uen;
            g_peA[bn*64 + tid] = s_v[tid] - uen;
            g_subA[(bn*64 + tid)*2    ] = m0;
            g_subA[(bn*64 + tid)*2 + 1] = m1;
        }
        __syncthreads();
        int r = (bid & 3)*16 + (tid >> 5), q = tid & 31;
        const float4* X = (const float4*)((bn & 1) ? g_Q : g_P);
        float4 a = X[((size_t)(bn*2    )*128 + s_m0[r])*32 + q];
        float4 b = X[((size_t)(bn*2 + 1)*128 + s_m1[r])*32 + q];
        ((float4*)g_H)[((size_t)bn*64 + r)*32 + q] =
            make_float4((a.x+b.x)*0.5f, (a.y+b.y)*0.5f, (a.z+b.z)*0.5f, (a.w+b.w)*0.5f);
    }
    megabar(2);

    // ===== Phase E: level-1 strip scores + strip top-64 (128 blocks) =====
    {
        int bn = bid >> 3, st = bid & 7, m0off = st * 8;
        ull* sH0p  = smu;                 // 64 x 9
        ull* sH1p  = sH0p + 64*9;         // 64 x 65
        ull* sw2h  = sH1p + 64*65;        // 64
        ull* svals = sw2h + 64;           // 512
        float* sb0 = (float*)(svals + 512); // 8
        float* sb1 = sb0 + 8;               // 64

        const float* h0 = g_H + (size_t)(2*bn  )*64*128 + (size_t)m0off*128;
        const float* h1 = g_H + (size_t)(2*bn+1)*64*128;
        {
            int m = tid >> 6, hp = tid & 63;
            float2 v = *(const float2*)(h0 + m*128 + 2*hp);
            sH0p[hp*9 + m] = pk2(v.x, v.y);
        }
        for (int i = tid; i < 64*64; i += 512) {
            int m = i >> 6, hp = i & 63;
            float2 v = *(const float2*)(h1 + m*128 + 2*hp);
            sH1p[hp*65 + m] = pk2(v.x + bp1[2*hp], v.y + bp1[2*hp+1]);
        }
        if (tid < 64) sw2h[tid] = pk2(0.5f*Wp2[2*tid], 0.5f*Wp2[2*tid+1]);
        float b2 = bp2[0];
        if (tid >= 64 && tid < 72)
            sb0[tid-64] = g_ueA[(2*bn)*64 + m0off + tid-64]
                        + g_peA[(2*bn)*64 + m0off + tid-64] - b2;
        if (tid >= 128 && tid < 192) {
            int m = tid - 128;
            sb1[m] = g_ueA[(2*bn+1)*64 + m] + g_peA[(2*bn+1)*64 + m];
        }
        __syncthreads();

        int m0l = tid >> 6, m1 = tid & 63;
        ull acc = 0ull;
        for (int hp = 0; hp < 64; hp++) {
            ull s = add2(sH0p[hp*9 + m0l], sH1p[hp*65 + m1]);
            s = add2(s, s & ABS2);
            fma2(acc, s, sw2h[hp]);
        }
        float lo, hi; upk2(acc, lo, hi);
        float val = sb0[m0l] + sb1[m1] - (lo + hi);
        int gidx = (m0off + m0l) * 64 + m1;
        ull c = ((ull)fkey(val) << 32) | (unsigned)gidx;
        svals[tid] = c;
        __syncthreads();
        int rank = 0;
        #pragma unroll 16
        for (int i = 0; i < 512; i++) rank += (svals[i] < c) ? 1 : 0;
        if (rank < 64) g_cand[bn*512 + st*64 + rank] = c;
    }
    megabar(3);

    // ===== Phase F+G: level-1 merge (x8 redundant) + H2 gather =====
    {
        int bn = bid >> 3;
        ull*   scand = smu;                 // 512
        int*   s_m0  = (int*)(scand + 512); // 64
        int*   s_m1  = s_m0 + 64;           // 64
        float* s_v   = (float*)(s_m1 + 64); // 64
        int*   s_sub = (int*)(s_v + 64);    // 256
        scand[tid] = g_cand[bn*512 + tid];
        __syncthreads();
        {
            ull c = scand[tid]; int rank = 0;
            #pragma unroll 16
            for (int i = 0; i < 512; i++) rank += (scand[i] < c) ? 1 : 0;
            if (rank < 64) {
                int j = (int)(c & 0xFFFFFFFFu);
                s_m0[rank] = j >> 6; s_m1[rank] = j & 63;
                s_v[rank] = unfkey((unsigned)(c >> 32));
            }
        }
        __syncthreads();
        if (tid < 64) {
            int m0 = s_m0[tid], m1 = s_m1[tid];
            float uen = g_ueA[(2*bn)*64 + m0] + g_ueA[(2*bn+1)*64 + m1];
            g_ueB[bn*64 + tid] = uen;
            g_peB[bn*64 + tid] = s_v[tid] - uen;
            int a0 = g_subA[((2*bn)*64 + m0)*2], a1 = g_subA[((2*bn)*64 + m0)*2 + 1];
            int b0 = g_subA[((2*bn+1)*64 + m1)*2], b1 = g_subA[((2*bn+1)*64 + m1)*2 + 1];
            s_sub[tid*4+0] = a0; s_sub[tid*4+1] = a1;
            s_sub[tid*4+2] = b0; s_sub[tid*4+3] = b1;
            g_subB[(bn*64 + tid)*4 + 0] = a0;
            g_subB[(bn*64 + tid)*4 + 1] = a1;
            g_subB[(bn*64 + tid)*4 + 2] = b0;
            g_subB[(bn*64 + tid)*4 + 3] = b1;
        }
        __syncthreads();
        if (tid < 256) {
            int r = (bid & 7)*8 + (tid >> 5), q = tid & 31;
            const float4* X = (const float4*)((bn & 1) ? g_Q : g_P);
            float4 s = make_float4(0.f, 0.f, 0.f, 0.f);
            #pragma unroll
            for (int i = 0; i < 4; i++) {
                float4 v = X[((size_t)(bn*4 + i)*128 + s_sub[r*4 + i])*32 + q];
                s.x += v.x; s.y += v.y; s.z += v.z; s.w += v.w;
            }
            ((float4*)g_H2)[((size_t)bn*64 + r)*32 + q] =
                make_float4(s.x*0.25f, s.y*0.25f, s.z*0.25f, s.w*0.25f);
        }
    }
    megabar(4);

    // ===== Phase H: level-2 strip argmin + fused final (32 blocks) =====
    if (bid < 32) {
        int bn = bid >> 2, m0off = (bid & 3) * 16;
        ull* sH0p = smu;                  // 64 x 17
        ull* sH1p = sH0p + 64*17;         // 64 x 65
        ull* sw2h = sH1p + 64*65;         // 64
        float* sb0 = (float*)(sw2h + 64); // 16
        float* sb1 = sb0 + 16;            // 64
        __shared__ ull hw[16];

        const float* h0 = g_H2 + (size_t)(2*bn  )*64*128 + (size_t)m0off*128;
        const float* h1 = g_H2 + (size_t)(2*bn+1)*64*128;
        for (int i = tid; i < 16*64; i += 512) {
            int m = i >> 6, hp = i & 63;
            float2 v = *(const float2*)(h0 + m*128 + 2*hp);
            sH0p[hp*17 + m] = pk2(v.x, v.y);
        }
        for (int i = tid; i < 64*64; i += 512) {
            int m = i >> 6, hp = i & 63;
            float2 v = *(const float2*)(h1 + m*128 + 2*hp);
            sH1p[hp*65 + m] = pk2(v.x + bp1[2*hp], v.y + bp1[2*hp+1]);
        }
        if (tid < 64) sw2h[tid] = pk2(0.5f*Wp2[2*tid], 0.5f*Wp2[2*tid+1]);
        float b2 = bp2[0];
        if (tid >= 64 && tid < 80)
            sb0[tid-64] = g_ueB[(2*bn)*64 + m0off + tid-64]
                        + g_peB[(2*bn)*64 + m0off + tid-64] - b2;
        if (tid >= 128 && tid < 192) {
            int m = tid - 128;
            sb1[m] = g_ueB[(2*bn+1)*64 + m] + g_peB[(2*bn+1)*64 + m];
        }
        __syncthreads();

        int m0l = tid >> 6, m1 = tid & 63;
        ull acc[2] = {0ull, 0ull};
        for (int hp = 0; hp < 64; hp++) {
            ull bb = sH1p[hp*65 + m1];
            ull wp = sw2h[hp];
            #pragma unroll
            for (int e = 0; e < 2; e++) {
                ull s = add2(sH0p[hp*17 + m0l + 8*e], bb);
                s = add2(s, s & ABS2);
                fma2(acc[e], s, wp);
            }
        }
        ull mbest = ~0ull;
        #pragma unroll
        for (int e = 0; e < 2; e++) {
            float lo, hi; upk2(acc[e], lo, hi);
            float val = sb0[m0l + 8*e] + sb1[m1] - (lo + hi);
            int gidx = (m0off + m0l + 8*e) * 64 + m1;
            mbest = umin64(mbest, ((ull)fkey(val) << 32) | (unsigned)gidx);
        }
        #pragma unroll
        for (int o = 16; o; o >>= 1) mbest = umin64(mbest, __shfl_down_sync(0xffffffffu, mbest, o));
        if ((tid & 31) == 0) hw[tid >> 5] = mbest;
        __syncthreads();
        if (tid == 0) {
            ull mm = ~0ull;
            #pragma unroll
            for (int w = 0; w < 16; w++) mm = umin64(mm, hw[w]);
            asm volatile("red.global.min.u64 [%0], %1;" :: "l"(&g_part[bn]), "l"(mm) : "memory");
            unsigned old;
            asm volatile("atom.acq_rel.gpu.global.add.u32 %0, [%1], %2;"
                         : "=r"(old) : "l"(&g_done[bn]), "r"(1u) : "memory");
            if (old == 3u) {
                ull fin;
                asm volatile("ld.acquire.gpu.global.u64 %0, [%1];"
                             : "=l"(fin) : "l"(&g_part[bn]) : "memory");
                int j = (int)(fin & 0xFFFFFFFFu);
                int m0 = j >> 6, m1w = j & 63;
                #pragma unroll
                for (int s = 0; s < 4; s++) {
                    d_out[bn*8 + s]     = (float)g_subB[((2*bn)*64 + m0)*4 + s];
                    d_out[bn*8 + 4 + s] = (float)g_subB[((2*bn+1)*64 + m1w)*4 + s];
                }
            }
        }
    }
}

// ---------------- launch ----------------
extern "C" void kernel_launch(void* const* d_in, const int* in_sizes, int n_in,
                              void* d_out, int out_size)
{
    const float* pos  = (const float*)d_in[0];
    const float* neg  = (const float*)d_in[1];
    const int*   pcls = (const int*)  d_in[2];
    const int*   tcls = (const int*)  d_in[3];
    const float* Wp1  = (const float*)d_in[4];
    const float* bp1  = (const float*)d_in[5];
    const float* Wp2  = (const float*)d_in[6];
    const float* bp2  = (const float*)d_in[7];
    const float* Wu1  = (const float*)d_in[8];
    const float* bu1  = (const float*)d_in[9];
    const float* Wu2  = (const float*)d_in[10];
    const float* bu2  = (const float*)d_in[11];
    float* out = (float*)d_out;

    // max dynamic smem = phase B: 10496 ull + 160 f + 4096 int = 100,992 B
    size_t smM = (size_t)10496*8 + 160*4 + 4096*4;

    cudaFuncSetAttribute(mega_kernel, cudaFuncAttributeMaxDynamicSharedMemorySize, (int)smM);

    gemm_all<<<dim3(64, 4), 256>>>(pos, neg, Wp1, Wu1);
    mega_kernel<<<NBLK, 512, smM>>>(bp1, Wp2, bp2, bu1, Wu2, bu2, pcls, tcls, out);
}